// round 9
// baseline (speedup 1.0000x reference)
#include <cuda_runtime.h>
#include <cuda_fp16.h>
#include <cstdint>

#define B_ 4
#define L_ 2048
#define D_ 512
#define H_ 8
#define DH_ 64
#define OUT_ELEMS (B_ * L_ * D_)          // 4194304
#define LOG2E_DIV32 0.04507129744f         // log2(e)/32

// Scratch (__device__ globals; allocation-free rule)
__device__ __half  g_qin[OUT_ELEMS];                // fp16 inputs
__device__ __half  g_kin[OUT_ELEMS];
__device__ __half  g_vin[OUT_ELEMS];
__device__ __half  g_wq[D_ * D_], g_wk[D_ * D_], g_wv[D_ * D_], g_wo[D_ * D_];
__device__ __half  g_qh[OUT_ELEMS];                 // fp16 projections
__device__ __half  g_kh[OUT_ELEMS];
__device__ __half  g_vh[OUT_ELEMS];
__device__ __half  g_ctxh[OUT_ELEMS];               // fp16 attention context
__device__ uint8_t g_mask8[(size_t)B_ * L_ * L_];   // 16.8 MB (fits L2)
__device__ __half  g_eh[(size_t)B_ * H_ * L_ * L_]; // 268 MB unnormalized e

// ---------------------------------------------------------------------------
// helpers
// ---------------------------------------------------------------------------
__device__ __forceinline__ void mma_f16(float4& d, uint32_t a0, uint32_t a1,
                                        uint32_t a2, uint32_t a3,
                                        uint32_t b0, uint32_t b1) {
    asm volatile(
        "mma.sync.aligned.m16n8k16.row.col.f32.f16.f16.f32 "
        "{%0,%1,%2,%3}, {%4,%5,%6,%7}, {%8,%9}, {%0,%1,%2,%3};"
        : "+f"(d.x), "+f"(d.y), "+f"(d.z), "+f"(d.w)
        : "r"(a0), "r"(a1), "r"(a2), "r"(a3), "r"(b0), "r"(b1));
}
__device__ __forceinline__ void ldsm4(uint32_t& r0, uint32_t& r1, uint32_t& r2,
                                      uint32_t& r3, uint32_t addr) {
    asm volatile("ldmatrix.sync.aligned.m8n8.x4.shared.b16 {%0,%1,%2,%3}, [%4];"
                 : "=r"(r0), "=r"(r1), "=r"(r2), "=r"(r3) : "r"(addr));
}
__device__ __forceinline__ void ldsm4t(uint32_t& r0, uint32_t& r1, uint32_t& r2,
                                       uint32_t& r3, uint32_t addr) {
    asm volatile("ldmatrix.sync.aligned.m8n8.x4.trans.shared.b16 {%0,%1,%2,%3}, [%4];"
                 : "=r"(r0), "=r"(r1), "=r"(r2), "=r"(r3) : "r"(addr));
}
__device__ __forceinline__ void cpa16(uint32_t s, const void* g) {
    asm volatile("cp.async.cg.shared.global [%0], [%1], 16;" :: "r"(s), "l"(g));
}
__device__ __forceinline__ void cpcommit() {
    asm volatile("cp.async.commit_group;" ::: "memory");
}
template <int N> __device__ __forceinline__ void cpwait() {
    asm volatile("cp.async.wait_group %0;" :: "n"(N) : "memory");
}

// ---------------------------------------------------------------------------
// prep: one kernel for mask pack + all fp32->fp16 converts.
// Segmented 1-D grid:
//   [0, 16384)          mask int32 -> uint8   (4.19M uchar4)
//   [16384, 28672)      Q,K,V converts        (3 x 4096 blocks, uint2 each)
//   [28672, 29696)      Wq,Wk,Wv,Wo converts  (4 x 256 blocks)
// ---------------------------------------------------------------------------
__global__ __launch_bounds__(256)
void prep(const int* __restrict__ m,
          const float* __restrict__ Q, const float* __restrict__ K,
          const float* __restrict__ V, const float* __restrict__ Wq,
          const float* __restrict__ Wk, const float* __restrict__ Wv,
          const float* __restrict__ Wo) {
    const int bx = blockIdx.x;
    if (bx < 16384) {
        const size_t i = (size_t)bx * 256 + threadIdx.x;
        const int4 v = reinterpret_cast<const int4*>(m)[i];
        uchar4 o;
        o.x = v.x ? 1 : 0; o.y = v.y ? 1 : 0; o.z = v.z ? 1 : 0; o.w = v.w ? 1 : 0;
        reinterpret_cast<uchar4*>(g_mask8)[i] = o;
        return;
    }
    const float* s;
    __half* d;
    size_t i;
    if (bx < 16384 + 3 * 4096) {
        const int seg = (bx - 16384) >> 12;          // /4096
        const int b2 = (bx - 16384) & 4095;
        s = (seg == 0) ? Q : (seg == 1) ? K : V;
        d = (seg == 0) ? g_qin : (seg == 1) ? g_kin : g_vin;
        i = (size_t)b2 * 256 + threadIdx.x;
    } else {
        const int seg = (bx - 16384 - 12288) >> 8;   // /256
        const int b2 = (bx - 16384 - 12288) & 255;
        s = (seg == 0) ? Wq : (seg == 1) ? Wk : (seg == 2) ? Wv : Wo;
        d = (seg == 0) ? g_wq : (seg == 1) ? g_wk : (seg == 2) ? g_wv : g_wo;
        i = (size_t)b2 * 256 + threadIdx.x;
    }
    const float4 v = reinterpret_cast<const float4*>(s)[i];
    __half2 h0 = __floats2half2_rn(v.x, v.y);
    __half2 h1 = __floats2half2_rn(v.z, v.w);
    uint2 o;
    o.x = *(uint32_t*)&h0;
    o.y = *(uint32_t*)&h1;
    reinterpret_cast<uint2*>(d)[i] = o;
}

// ---------------------------------------------------------------------------
// fp16 GEMM: C[M,512] = A[M,512] @ W[512,512] + bias (fp32 accum/bias).
// Block 128x64, 8 warps (4m x 2n), warp 32x32, k-stage 64, cp.async 2-stage.
// ---------------------------------------------------------------------------
__device__ __forceinline__ void hgemm_issue(const __half* A, const __half* W,
                                            int m0, int n0, uint32_t as_s,
                                            uint32_t bs_s, int ki, int buf,
                                            int tid) {
    const __half* Ap = A + (size_t)m0 * 512 + ki * 64;
#pragma unroll
    for (int t = 0; t < 4; t++) {
        const int s = tid + 256 * t;
        const int r = s >> 3, c = (s & 7) << 3;
        cpa16(as_s + (uint32_t)((buf * 128 * 72 + r * 72 + c) * 2),
              Ap + (size_t)r * 512 + c);
    }
    const __half* Wp = W + (size_t)ki * 64 * 512 + n0;
#pragma unroll
    for (int t = 0; t < 2; t++) {
        const int s = tid + 256 * t;
        const int r = s >> 3, c = (s & 7) << 3;
        cpa16(bs_s + (uint32_t)((buf * 64 * 72 + r * 72 + c) * 2),
              Wp + (size_t)r * 512 + c);
    }
    cpcommit();
}

template <typename OutT>
__global__ __launch_bounds__(256, 2)
void hgemm(const __half* __restrict__ A, const __half* __restrict__ W,
           const float* __restrict__ bias, OutT* __restrict__ C) {
    extern __shared__ __half smh[];
    __half* Ah = smh;                  // [2][128][72]
    __half* Wh = smh + 2 * 128 * 72;   // [2][64][72]

    const int tid = threadIdx.x, l = tid & 31, w = tid >> 5;
    const int mg = w >> 1, ng = w & 1;
    const int wm = mg * 32, wn = ng * 32;
    const int lr = l >> 2, lc = l & 3;
    const int m0 = blockIdx.y << 7, n0 = blockIdx.x << 6;

    const uint32_t as_s = (uint32_t)__cvta_generic_to_shared(Ah);
    const uint32_t bs_s = (uint32_t)__cvta_generic_to_shared(Wh);

    const int a_row = (l & 15), a_col = (l >> 4) << 3;
    const int vb_row = (((l >> 3) & 1) << 3) + (l & 7);
    const int vb_col = (l >> 4) << 3;

    float4 acc[2][4];
#pragma unroll
    for (int m = 0; m < 2; m++)
#pragma unroll
        for (int j = 0; j < 4; j++) acc[m][j] = make_float4(0.f, 0.f, 0.f, 0.f);

    hgemm_issue(A, W, m0, n0, as_s, bs_s, 0, 0, tid);

    for (int ki = 0; ki < 8; ki++) {
        if (ki + 1 < 8) {
            hgemm_issue(A, W, m0, n0, as_s, bs_s, ki + 1, (ki + 1) & 1, tid);
            cpwait<1>();
        } else {
            cpwait<0>();
        }
        __syncthreads();

        const int buf = ki & 1;
        const uint32_t a0b = as_s + (uint32_t)((buf * 128 * 72 + (wm + a_row) * 72 + a_col) * 2);
        const uint32_t a1b = a0b + 16 * 72 * 2;
        const uint32_t wb = bs_s + (uint32_t)((buf * 64 * 72) * 2);

#pragma unroll
        for (int kc = 0; kc < 4; kc++) {
            uint32_t a0[4], a1[4];
            ldsm4(a0[0], a0[1], a0[2], a0[3], a0b + kc * 32);
            ldsm4(a1[0], a1[1], a1[2], a1[3], a1b + kc * 32);
#pragma unroll
            for (int j = 0; j < 2; j++) {
                uint32_t b0, b1, b2, b3;
                ldsm4t(b0, b1, b2, b3,
                       wb + (uint32_t)(((kc * 16 + vb_row) * 72 + wn + 16 * j + vb_col) * 2));
                mma_f16(acc[0][2 * j],     a0[0], a0[1], a0[2], a0[3], b0, b1);
                mma_f16(acc[1][2 * j],     a1[0], a1[1], a1[2], a1[3], b0, b1);
                mma_f16(acc[0][2 * j + 1], a0[0], a0[1], a0[2], a0[3], b2, b3);
                mma_f16(acc[1][2 * j + 1], a1[0], a1[1], a1[2], a1[3], b2, b3);
            }
        }
        __syncthreads();
    }

#pragma unroll
    for (int m = 0; m < 2; m++)
#pragma unroll
        for (int j = 0; j < 4; j++) {
            const int rg = m0 + wm + 16 * m + lr;
            const int cg = n0 + wn + 8 * j + 2 * lc;
            const float2 bv = *(const float2*)&bias[cg];
            if constexpr (sizeof(OutT) == 2) {
                *(__half2*)&C[(size_t)rg * 512 + cg] =
                    __floats2half2_rn(acc[m][j].x + bv.x, acc[m][j].y + bv.y);
                *(__half2*)&C[(size_t)(rg + 8) * 512 + cg] =
                    __floats2half2_rn(acc[m][j].z + bv.x, acc[m][j].w + bv.y);
            } else {
                *(float2*)&C[(size_t)rg * 512 + cg] =
                    make_float2(acc[m][j].x + bv.x, acc[m][j].y + bv.y);
                *(float2*)&C[(size_t)(rg + 8) * 512 + cg] =
                    make_float2(acc[m][j].z + bv.x, acc[m][j].w + bv.y);
            }
        }
}

// ---------------------------------------------------------------------------
// fp16 fused attention + embedded normalize. CTA = (bh, 128 q rows);
// warp owns 16 q-rows x 64 kv. Mainloop: QK -> masked exp -> es smem
// (+register repack) -> coalesced unnormalized-e store + PV from registers.
// Tail: rowsum -> inv, then re-read own e rows (L2-warm) and write
// normalized fp32 attn directly. ctx (fp16) scaled by 1/rowsum.
// smem halves: qs[128][72] + ks[2][64][72] + vs[2][64][72] + es[128][72]
//              (+ red 128 f32) = 74240 B
// ---------------------------------------------------------------------------
__global__ __launch_bounds__(256, 2)
void attn_fp16(float* __restrict__ attn) {
    extern __shared__ __half smh[];
    __half* qs = smh;                  // [128][72]
    __half* ks = qs + 128 * 72;        // [2][64][72]
    __half* vs = ks + 2 * 64 * 72;     // [2][64][72]
    __half* es = vs + 2 * 64 * 72;     // [128][72] (64 cols used)
    float* red = (float*)(es + 128 * 72);   // [128]

    const int tid = threadIdx.x, l = tid & 31, w = tid >> 5;
    const int wq = w * 16;
    const int g = l >> 2, tig = l & 3;
    const int qt = blockIdx.x, bh = blockIdx.y, b = bh >> 3;
    const int q0 = qt * 128;

    const __half* qg = g_qh + ((size_t)bh * L_ + q0) * DH_;
    const __half* kg = g_kh + (size_t)bh * L_ * DH_;
    const __half* vg = g_vh + (size_t)bh * L_ * DH_;
    const uint8_t* mb = g_mask8 + (size_t)b * L_ * L_;

    const uint32_t qs_s = (uint32_t)__cvta_generic_to_shared(qs);
    const uint32_t ks_s = (uint32_t)__cvta_generic_to_shared(ks);
    const uint32_t vs_s = (uint32_t)__cvta_generic_to_shared(vs);

#define ISSUE_K(kt_, buf_)                                                     \
    do {                                                                       \
        _Pragma("unroll")                                                      \
        for (int t = 0; t < 2; t++) {                                          \
            const int s = tid + 256 * t;                                       \
            const int r = s >> 3, c = (s & 7) << 3;                            \
            cpa16(ks_s + (uint32_t)(((buf_) * 64 * 72 + r * 72 + c) * 2),      \
                  kg + (size_t)((kt_) * 64 + r) * DH_ + c);                    \
        }                                                                      \
        cpcommit();                                                            \
    } while (0)
#define ISSUE_V(kt_, buf_)                                                     \
    do {                                                                       \
        _Pragma("unroll")                                                      \
        for (int t = 0; t < 2; t++) {                                          \
            const int s = tid + 256 * t;                                       \
            const int r = s >> 3, c = (s & 7) << 3;                            \
            cpa16(vs_s + (uint32_t)(((buf_) * 64 * 72 + r * 72 + c) * 2),      \
                  vg + (size_t)((kt_) * 64 + r) * DH_ + c);                    \
        }                                                                      \
        cpcommit();                                                            \
    } while (0)

    // Q (group), K0 (group), V0 (group)
#pragma unroll
    for (int t = 0; t < 4; t++) {
        const int s = tid + 256 * t;
        const int r = s >> 3, c = (s & 7) << 3;
        cpa16(qs_s + (uint32_t)((r * 72 + c) * 2), qg + (size_t)r * DH_ + c);
    }
    cpcommit();
    ISSUE_K(0, 0);
    ISSUE_V(0, 0);

    // ldmatrix lane addressing
    const int a_row = wq + (l & 15);
    const int a_col = (l >> 4) << 3;
    const int kb_row = ((l >> 4) << 3) + (l & 7);
    const int kb_col = ((l >> 3) & 1) << 3;
    const int vb_row = (((l >> 3) & 1) << 3) + (l & 7);
    const int vb_col = (l >> 4) << 3;

    cpwait<2>();
    __syncthreads();

    uint32_t qa[4][4];
    const uint32_t qaddr = qs_s + (uint32_t)((a_row * 72 + a_col) * 2);
#pragma unroll
    for (int kc = 0; kc < 4; kc++)
        ldsm4(qa[kc][0], qa[kc][1], qa[kc][2], qa[kc][3], qaddr + kc * 32);

    float4 ctx[8];
#pragma unroll
    for (int j = 0; j < 8; j++) ctx[j] = make_float4(0.f, 0.f, 0.f, 0.f);
    float rs0 = 0.f, rs1 = 0.f;

    const int rg0 = q0 + wq + g;
    const int rg1 = rg0 + 8;
    const int er0 = wq + g;            // local e rows
    __half* eg = g_eh + ((size_t)bh * L_ + q0) * L_;

    for (int kt = 0; kt < 32; kt++) {
        const int buf = kt & 1;
        cpwait<1>();
        __syncthreads();

        // ---- QK^T ----
        float4 acc[8];
#pragma unroll
        for (int j = 0; j < 8; j++) acc[j] = make_float4(0.f, 0.f, 0.f, 0.f);

        const uint32_t ksb = ks_s + (uint32_t)(buf * 64 * 72 * 2);
#pragma unroll
        for (int kc = 0; kc < 4; kc++) {
#pragma unroll
            for (int q4 = 0; q4 < 4; q4++) {
                uint32_t b0, b1, b2, b3;
                ldsm4(b0, b1, b2, b3,
                      ksb + (uint32_t)(((q4 * 16 + kb_row) * 72 + kc * 16 + kb_col) * 2));
                mma_f16(acc[2 * q4],     qa[kc][0], qa[kc][1], qa[kc][2], qa[kc][3], b0, b1);
                mma_f16(acc[2 * q4 + 1], qa[kc][0], qa[kc][1], qa[kc][2], qa[kc][3], b2, b3);
            }
        }

        if (kt + 1 < 32) ISSUE_K(kt + 1, buf ^ 1);

        // ---- epilogue: masked exp -> es smem + register repack ----
        uint32_t plo[8], phi[8];
        const uint8_t* m0p = mb + (size_t)rg0 * L_ + kt * 64 + 2 * tig;
        const uint8_t* m1p = mb + (size_t)rg1 * L_ + kt * 64 + 2 * tig;
#pragma unroll
        for (int j = 0; j < 8; j++) {
            const int co = 8 * j;
            const uchar2 m0 = *(const uchar2*)(m0p + co);
            const uchar2 m1 = *(const uchar2*)(m1p + co);
            const float e0 = m0.x ? exp2f(acc[j].x * LOG2E_DIV32) : 0.f;
            const float e1 = m0.y ? exp2f(acc[j].y * LOG2E_DIV32) : 0.f;
            const float e2 = m1.x ? exp2f(acc[j].z * LOG2E_DIV32) : 0.f;
            const float e3 = m1.y ? exp2f(acc[j].w * LOG2E_DIV32) : 0.f;
            rs0 += e0 + e1;
            rs1 += e2 + e3;
            const __half2 h0 = __floats2half2_rn(e0, e1);
            const __half2 h1 = __floats2half2_rn(e2, e3);
            plo[j] = *(const uint32_t*)&h0;
            phi[j] = *(const uint32_t*)&h1;
            const int cl = co + 2 * tig;
            *(__half2*)&es[er0 * 72 + cl] = h0;
            *(__half2*)&es[(er0 + 8) * 72 + cl] = h1;
        }

        if (kt + 1 < 32) cpwait<1>(); else cpwait<0>();
        __syncthreads();   // publishes es + vs

        // ---- P @ V (A from registers) ----
        const uint32_t vsb = vs_s + (uint32_t)(buf * 64 * 72 * 2);
#pragma unroll
        for (int kc = 0; kc < 4; kc++) {
            const uint32_t a0 = plo[2 * kc], a1 = phi[2 * kc];
            const uint32_t a2 = plo[2 * kc + 1], a3 = phi[2 * kc + 1];
#pragma unroll
            for (int q4 = 0; q4 < 4; q4++) {
                uint32_t b0, b1, b2, b3;
                ldsm4t(b0, b1, b2, b3,
                       vsb + (uint32_t)(((kc * 16 + vb_row) * 72 + q4 * 16 + vb_col) * 2));
                mma_f16(ctx[2 * q4],     a0, a1, a2, a3, b0, b1);
                mma_f16(ctx[2 * q4 + 1], a0, a1, a2, a3, b2, b3);
            }
        }

        // ---- coalesced e tile store: 128 rows x 64 cols fp16 ----
#pragma unroll
        for (int t = 0; t < 4; t++) {
            const int s = tid + 256 * t;
            const int r = s >> 3, c = (s & 7) << 3;
            *(uint4*)(eg + (size_t)r * L_ + kt * 64 + c) = *(const uint4*)&es[r * 72 + c];
        }

        if (kt + 1 < 32) ISSUE_V(kt + 1, buf ^ 1);
    }

    // ---- rowsum reduce -> inv (smem) ----
    rs0 += __shfl_xor_sync(0xffffffffu, rs0, 1);
    rs0 += __shfl_xor_sync(0xffffffffu, rs0, 2);
    rs1 += __shfl_xor_sync(0xffffffffu, rs1, 1);
    rs1 += __shfl_xor_sync(0xffffffffu, rs1, 2);
    if (tig == 0) {
        red[wq + g] = rs0;
        red[wq + 8 + g] = rs1;
    }
    __syncthreads();
    if (tid < 128) {
        const float s = red[tid];
        red[tid] = (s > 0.f) ? (1.f / s) : 0.f;
    }
    __syncthreads();
    const float iv0 = red[wq + g];
    const float iv1 = red[wq + 8 + g];

    // ---- ctx write (normalized fp16) ----
#pragma unroll
    for (int j = 0; j < 8; j++) {
        const int cd = 8 * j + 2 * tig;
        *(__half2*)&g_ctxh[((size_t)bh * L_ + rg0) * DH_ + cd] =
            __floats2half2_rn(ctx[j].x * iv0, ctx[j].y * iv0);
        *(__half2*)&g_ctxh[((size_t)bh * L_ + rg1) * DH_ + cd] =
            __floats2half2_rn(ctx[j].z * iv1, ctx[j].w * iv1);
    }

    // ---- embedded normalize: re-read own e rows (L2-warm), write fp32 attn.
    // One row per iteration: 256 threads x 8 halves = 2048 cols.
    float* adst = attn + ((size_t)bh * L_ + q0) * L_;
    const int ecol = tid * 8;
#pragma unroll 4
    for (int r = 0; r < 128; r++) {
        const float iv = red[r];
        const uint4 u = *(const uint4*)(eg + (size_t)r * L_ + ecol);
        const float2 f0 = __half22float2(*(const __half2*)&u.x);
        const float2 f1 = __half22float2(*(const __half2*)&u.y);
        const float2 f2 = __half22float2(*(const __half2*)&u.z);
        const float2 f3 = __half22float2(*(const __half2*)&u.w);
        float4 o0 = make_float4(f0.x * iv, f0.y * iv, f1.x * iv, f1.y * iv);
        float4 o1 = make_float4(f2.x * iv, f2.y * iv, f3.x * iv, f3.y * iv);
        *(float4*)(adst + (size_t)r * L_ + ecol) = o0;
        *(float4*)(adst + (size_t)r * L_ + ecol + 4) = o1;
    }
#undef ISSUE_K
#undef ISSUE_V
}

// ---------------------------------------------------------------------------
extern "C" void kernel_launch(void* const* d_in, const int* in_sizes, int n_in,
                              void* d_out, int out_size) {
    const float* Q  = (const float*)d_in[0];
    const float* K  = (const float*)d_in[1];
    const float* V  = (const float*)d_in[2];
    const int*   Mk = (const int*)d_in[3];
    const float* Wq = (const float*)d_in[4];
    const float* bq = (const float*)d_in[5];
    const float* Wk = (const float*)d_in[6];
    const float* bk = (const float*)d_in[7];
    const float* Wv = (const float*)d_in[8];
    const float* bv = (const float*)d_in[9];
    const float* Wo = (const float*)d_in[10];
    const float* bo = (const float*)d_in[11];

    __half *qin, *kin, *vin, *wq, *wk, *wv, *wo, *qh, *kh, *vh, *ctxh;
    cudaGetSymbolAddress((void**)&qin, g_qin);
    cudaGetSymbolAddress((void**)&kin, g_kin);
    cudaGetSymbolAddress((void**)&vin, g_vin);
    cudaGetSymbolAddress((void**)&wq, g_wq);
    cudaGetSymbolAddress((void**)&wk, g_wk);
    cudaGetSymbolAddress((void**)&wv, g_wv);
    cudaGetSymbolAddress((void**)&wo, g_wo);
    cudaGetSymbolAddress((void**)&qh, g_qh);
    cudaGetSymbolAddress((void**)&kh, g_kh);
    cudaGetSymbolAddress((void**)&vh, g_vh);
    cudaGetSymbolAddress((void**)&ctxh, g_ctxh);

    float* out  = (float*)d_out;
    float* attn = out + OUT_ELEMS;   // concat(out, attn_dist)

    const int smem_gemm = (2 * 128 * 72 + 2 * 64 * 72) * 2;                  // 55296
    const int smem_attn = (128 * 72 + 4 * 64 * 72 + 128 * 72) * 2 + 128 * 4; // 74240
    cudaFuncSetAttribute(hgemm<__half>, cudaFuncAttributeMaxDynamicSharedMemorySize, smem_gemm);
    cudaFuncSetAttribute(hgemm<float>, cudaFuncAttributeMaxDynamicSharedMemorySize, smem_gemm);
    cudaFuncSetAttribute(attn_fp16, cudaFuncAttributeMaxDynamicSharedMemorySize, smem_attn);

    prep<<<16384 + 3 * 4096 + 4 * 256, 256>>>(Mk, Q, K, V, Wq, Wk, Wv, Wo);

    const dim3 gg(8, 64);    // N/64, M/128
    hgemm<__half><<<gg, 256, smem_gemm>>>(qin, wq, bq, qh);
    hgemm<__half><<<gg, 256, smem_gemm>>>(kin, wk, bk, kh);
    hgemm<__half><<<gg, 256, smem_gemm>>>(vin, wv, bv, vh);

    const dim3 ga(16, 32);   // q-tiles of 128, b*h
    attn_fp16<<<ga, 256, smem_attn>>>(attn);

    hgemm<float><<<gg, 256, smem_gemm>>>(ctxh, wo, bo, out);
}

// round 10
// speedup vs baseline: 1.0774x; 1.0774x over previous
#include <cuda_runtime.h>
#include <cuda_fp16.h>
#include <cstdint>

#define B_ 4
#define L_ 2048
#define D_ 512
#define H_ 8
#define DH_ 64
#define OUT_ELEMS (B_ * L_ * D_)          // 4194304
#define LOG2E_DIV32 0.04507129744f         // log2(e)/32

// Scratch (__device__ globals; allocation-free rule)
__device__ __half   g_qin[OUT_ELEMS];               // fp16 inputs
__device__ __half   g_kin[OUT_ELEMS];
__device__ __half   g_vin[OUT_ELEMS];
__device__ __half   g_wq[D_ * D_], g_wk[D_ * D_], g_wv[D_ * D_], g_wo[D_ * D_];
__device__ __half   g_qh[OUT_ELEMS];                // fp16 projections
__device__ __half   g_kh[OUT_ELEMS];
__device__ __half   g_vh[OUT_ELEMS];
__device__ __half   g_ctxh[OUT_ELEMS];              // fp16 attention context
__device__ float    g_inv[B_ * H_ * L_];
__device__ uint32_t g_maskb[(size_t)B_ * L_ * L_ / 32];   // 2 MB bitmask
__device__ __half   g_eh[(size_t)B_ * H_ * L_ * L_];      // 268 MB unnormalized e

// ---------------------------------------------------------------------------
// helpers
// ---------------------------------------------------------------------------
__device__ __forceinline__ void mma_f16(float4& d, uint32_t a0, uint32_t a1,
                                        uint32_t a2, uint32_t a3,
                                        uint32_t b0, uint32_t b1) {
    asm volatile(
        "mma.sync.aligned.m16n8k16.row.col.f32.f16.f16.f32 "
        "{%0,%1,%2,%3}, {%4,%5,%6,%7}, {%8,%9}, {%0,%1,%2,%3};"
        : "+f"(d.x), "+f"(d.y), "+f"(d.z), "+f"(d.w)
        : "r"(a0), "r"(a1), "r"(a2), "r"(a3), "r"(b0), "r"(b1));
}
__device__ __forceinline__ void ldsm4(uint32_t& r0, uint32_t& r1, uint32_t& r2,
                                      uint32_t& r3, uint32_t addr) {
    asm volatile("ldmatrix.sync.aligned.m8n8.x4.shared.b16 {%0,%1,%2,%3}, [%4];"
                 : "=r"(r0), "=r"(r1), "=r"(r2), "=r"(r3) : "r"(addr));
}
__device__ __forceinline__ void ldsm4t(uint32_t& r0, uint32_t& r1, uint32_t& r2,
                                       uint32_t& r3, uint32_t addr) {
    asm volatile("ldmatrix.sync.aligned.m8n8.x4.trans.shared.b16 {%0,%1,%2,%3}, [%4];"
                 : "=r"(r0), "=r"(r1), "=r"(r2), "=r"(r3) : "r"(addr));
}
__device__ __forceinline__ void cpa16(uint32_t s, const void* g) {
    asm volatile("cp.async.cg.shared.global [%0], [%1], 16;" :: "r"(s), "l"(g));
}
__device__ __forceinline__ void cpcommit() {
    asm volatile("cp.async.commit_group;" ::: "memory");
}
template <int N> __device__ __forceinline__ void cpwait() {
    asm volatile("cp.async.wait_group %0;" :: "n"(N) : "memory");
}

// ---------------------------------------------------------------------------
// prep: mask -> bitmask (warp ballot) + all fp32->fp16 converts.
// Segments: [0,2048) bitpack | [2048,14336) Q,K,V | [14336,15360) weights
// ---------------------------------------------------------------------------
__global__ __launch_bounds__(256)
void prep(const int* __restrict__ m,
          const float* __restrict__ Q, const float* __restrict__ K,
          const float* __restrict__ V, const float* __restrict__ Wq,
          const float* __restrict__ Wk, const float* __restrict__ Wv,
          const float* __restrict__ Wo) {
    int bx = blockIdx.x;
    if (bx < 2048) {
        // each warp packs 1024 ints -> 32 uint32 words
        const int wg = bx * 8 + (threadIdx.x >> 5);
        const int lane = threadIdx.x & 31;
        const size_t base = (size_t)wg * 1024;
        uint32_t word = 0;
#pragma unroll
        for (int r = 0; r < 32; r++) {
            const int v = m[base + (size_t)r * 32 + lane];
            const unsigned bits = __ballot_sync(0xffffffffu, v != 0);
            if (lane == r) word = bits;
        }
        g_maskb[base / 32 + lane] = word;
        return;
    }
    bx -= 2048;
    const float* s;
    __half* d;
    size_t i;
    if (bx < 3 * 4096) {
        const int seg = bx >> 12;
        const int b2 = bx & 4095;
        s = (seg == 0) ? Q : (seg == 1) ? K : V;
        d = (seg == 0) ? g_qin : (seg == 1) ? g_kin : g_vin;
        i = (size_t)b2 * 256 + threadIdx.x;
    } else {
        bx -= 3 * 4096;
        const int seg = bx >> 8;
        const int b2 = bx & 255;
        s = (seg == 0) ? Wq : (seg == 1) ? Wk : (seg == 2) ? Wv : Wo;
        d = (seg == 0) ? g_wq : (seg == 1) ? g_wk : (seg == 2) ? g_wv : g_wo;
        i = (size_t)b2 * 256 + threadIdx.x;
    }
    const float4 v = reinterpret_cast<const float4*>(s)[i];
    __half2 h0 = __floats2half2_rn(v.x, v.y);
    __half2 h1 = __floats2half2_rn(v.z, v.w);
    uint2 o;
    o.x = *(uint32_t*)&h0;
    o.y = *(uint32_t*)&h1;
    reinterpret_cast<uint2*>(d)[i] = o;
}

// ---------------------------------------------------------------------------
// fp16 GEMM body: C[M,512] = A[M,512] @ W[512,512] + bias (fp32 accum/bias).
// Block 128x64 via (blockIdx.x, blockIdx.y), 8 warps, warp 32x32, k-stage 64.
// ---------------------------------------------------------------------------
__device__ __forceinline__ void hgemm_issue(const __half* A, const __half* W,
                                            int m0, int n0, uint32_t as_s,
                                            uint32_t bs_s, int ki, int buf,
                                            int tid) {
    const __half* Ap = A + (size_t)m0 * 512 + ki * 64;
#pragma unroll
    for (int t = 0; t < 4; t++) {
        const int s = tid + 256 * t;
        const int r = s >> 3, c = (s & 7) << 3;
        cpa16(as_s + (uint32_t)((buf * 128 * 72 + r * 72 + c) * 2),
              Ap + (size_t)r * 512 + c);
    }
    const __half* Wp = W + (size_t)ki * 64 * 512 + n0;
#pragma unroll
    for (int t = 0; t < 2; t++) {
        const int s = tid + 256 * t;
        const int r = s >> 3, c = (s & 7) << 3;
        cpa16(bs_s + (uint32_t)((buf * 64 * 72 + r * 72 + c) * 2),
              Wp + (size_t)r * 512 + c);
    }
    cpcommit();
}

template <typename OutT>
__device__ __forceinline__ void hgemm_body(const __half* __restrict__ A,
                                           const __half* __restrict__ W,
                                           const float* __restrict__ bias,
                                           OutT* __restrict__ C) {
    extern __shared__ __half smh[];
    __half* Ah = smh;                  // [2][128][72]
    __half* Wh = smh + 2 * 128 * 72;   // [2][64][72]

    const int tid = threadIdx.x, l = tid & 31, w = tid >> 5;
    const int mg = w >> 1, ng = w & 1;
    const int wm = mg * 32, wn = ng * 32;
    const int lr = l >> 2, lc = l & 3;
    const int m0 = blockIdx.y << 7, n0 = blockIdx.x << 6;

    const uint32_t as_s = (uint32_t)__cvta_generic_to_shared(Ah);
    const uint32_t bs_s = (uint32_t)__cvta_generic_to_shared(Wh);

    const int a_row = (l & 15), a_col = (l >> 4) << 3;
    const int vb_row = (((l >> 3) & 1) << 3) + (l & 7);
    const int vb_col = (l >> 4) << 3;

    float4 acc[2][4];
#pragma unroll
    for (int m = 0; m < 2; m++)
#pragma unroll
        for (int j = 0; j < 4; j++) acc[m][j] = make_float4(0.f, 0.f, 0.f, 0.f);

    hgemm_issue(A, W, m0, n0, as_s, bs_s, 0, 0, tid);

    for (int ki = 0; ki < 8; ki++) {
        if (ki + 1 < 8) {
            hgemm_issue(A, W, m0, n0, as_s, bs_s, ki + 1, (ki + 1) & 1, tid);
            cpwait<1>();
        } else {
            cpwait<0>();
        }
        __syncthreads();

        const int buf = ki & 1;
        const uint32_t a0b = as_s + (uint32_t)((buf * 128 * 72 + (wm + a_row) * 72 + a_col) * 2);
        const uint32_t a1b = a0b + 16 * 72 * 2;
        const uint32_t wb = bs_s + (uint32_t)((buf * 64 * 72) * 2);

#pragma unroll
        for (int kc = 0; kc < 4; kc++) {
            uint32_t a0[4], a1[4];
            ldsm4(a0[0], a0[1], a0[2], a0[3], a0b + kc * 32);
            ldsm4(a1[0], a1[1], a1[2], a1[3], a1b + kc * 32);
#pragma unroll
            for (int j = 0; j < 2; j++) {
                uint32_t b0, b1, b2, b3;
                ldsm4t(b0, b1, b2, b3,
                       wb + (uint32_t)(((kc * 16 + vb_row) * 72 + wn + 16 * j + vb_col) * 2));
                mma_f16(acc[0][2 * j],     a0[0], a0[1], a0[2], a0[3], b0, b1);
                mma_f16(acc[1][2 * j],     a1[0], a1[1], a1[2], a1[3], b0, b1);
                mma_f16(acc[0][2 * j + 1], a0[0], a0[1], a0[2], a0[3], b2, b3);
                mma_f16(acc[1][2 * j + 1], a1[0], a1[1], a1[2], a1[3], b2, b3);
            }
        }
        __syncthreads();
    }

#pragma unroll
    for (int m = 0; m < 2; m++)
#pragma unroll
        for (int j = 0; j < 4; j++) {
            const int rg = m0 + wm + 16 * m + lr;
            const int cg = n0 + wn + 8 * j + 2 * lc;
            const float2 bv = *(const float2*)&bias[cg];
            if constexpr (sizeof(OutT) == 2) {
                *(__half2*)&C[(size_t)rg * 512 + cg] =
                    __floats2half2_rn(acc[m][j].x + bv.x, acc[m][j].y + bv.y);
                *(__half2*)&C[(size_t)(rg + 8) * 512 + cg] =
                    __floats2half2_rn(acc[m][j].z + bv.x, acc[m][j].w + bv.y);
            } else {
                *(float2*)&C[(size_t)rg * 512 + cg] =
                    make_float2(acc[m][j].x + bv.x, acc[m][j].y + bv.y);
                *(float2*)&C[(size_t)(rg + 8) * 512 + cg] =
                    make_float2(acc[m][j].z + bv.x, acc[m][j].w + bv.y);
            }
        }
}

// ---------------------------------------------------------------------------
// proj3: all three projection GEMMs in one launch (z selects Q/K/V).
// ---------------------------------------------------------------------------
__global__ __launch_bounds__(256, 2)
void proj3(const float* __restrict__ bq, const float* __restrict__ bk,
           const float* __restrict__ bv) {
    if (blockIdx.z == 0)      hgemm_body<__half>(g_qin, g_wq, bq, g_qh);
    else if (blockIdx.z == 1) hgemm_body<__half>(g_kin, g_wk, bk, g_kh);
    else                      hgemm_body<__half>(g_vin, g_wv, bv, g_vh);
}

// ---------------------------------------------------------------------------
// epilogue: z=0 -> out-projection GEMM; z=1 -> rescale attn (concurrent).
// ---------------------------------------------------------------------------
__global__ __launch_bounds__(256, 2)
void epilogue(const float* __restrict__ bo, float* __restrict__ out,
              float* __restrict__ attn) {
    if (blockIdx.z == 0) {
        hgemm_body<float>(g_ctxh, g_wo, bo, out);
        return;
    }
    // rescale: 512 blocks x 128 rows each
    const int blk = blockIdx.y * 8 + blockIdx.x;
    const int tid = threadIdx.x;
#pragma unroll 4
    for (int rr = 0; rr < 128; rr++) {
        const int row = blk * 128 + rr;
        const float iv = g_inv[row];
        const uint4 u = reinterpret_cast<const uint4*>(g_eh + (size_t)row * L_)[tid];
        const float2 f0 = __half22float2(*(const __half2*)&u.x);
        const float2 f1 = __half22float2(*(const __half2*)&u.y);
        const float2 f2 = __half22float2(*(const __half2*)&u.z);
        const float2 f3 = __half22float2(*(const __half2*)&u.w);
        float4* dst = reinterpret_cast<float4*>(attn + (size_t)row * L_);
        dst[2 * tid] = make_float4(f0.x * iv, f0.y * iv, f1.x * iv, f1.y * iv);
        dst[2 * tid + 1] = make_float4(f2.x * iv, f2.y * iv, f3.x * iv, f3.y * iv);
    }
}

// ---------------------------------------------------------------------------
// fp16 fused attention (R8 structure, bitmask). CTA = (bh, 128 q rows);
// warp owns 16 q-rows x 64 kv. QK -> masked exp (bitmask) -> es smem
// (+register repack) -> coalesced unnormalized-e store + PV from registers.
// ---------------------------------------------------------------------------
__global__ __launch_bounds__(256, 2)
void attn_fp16(float* __restrict__ dummy) {
    extern __shared__ __half smh[];
    __half* qs = smh;                  // [128][72]
    __half* ks = qs + 128 * 72;        // [2][64][72]
    __half* vs = ks + 2 * 64 * 72;     // [2][64][72]
    __half* es = vs + 2 * 64 * 72;     // [128][72] (64 cols used)
    float* red = (float*)(es + 128 * 72);   // [128]

    const int tid = threadIdx.x, l = tid & 31, w = tid >> 5;
    const int wq = w * 16;
    const int g = l >> 2, tig = l & 3;
    const int qt = blockIdx.x, bh = blockIdx.y, b = bh >> 3;
    const int q0 = qt * 128;

    const __half* qg = g_qh + ((size_t)bh * L_ + q0) * DH_;
    const __half* kg = g_kh + (size_t)bh * L_ * DH_;
    const __half* vg = g_vh + (size_t)bh * L_ * DH_;
    const uint8_t* mbB = (const uint8_t*)g_maskb + ((size_t)b * L_ * L_ >> 3);

    const uint32_t qs_s = (uint32_t)__cvta_generic_to_shared(qs);
    const uint32_t ks_s = (uint32_t)__cvta_generic_to_shared(ks);
    const uint32_t vs_s = (uint32_t)__cvta_generic_to_shared(vs);

#define ISSUE_K(kt_, buf_)                                                     \
    do {                                                                       \
        _Pragma("unroll")                                                      \
        for (int t = 0; t < 2; t++) {                                          \
            const int s = tid + 256 * t;                                       \
            const int r = s >> 3, c = (s & 7) << 3;                            \
            cpa16(ks_s + (uint32_t)(((buf_) * 64 * 72 + r * 72 + c) * 2),      \
                  kg + (size_t)((kt_) * 64 + r) * DH_ + c);                    \
        }                                                                      \
        cpcommit();                                                            \
    } while (0)
#define ISSUE_V(kt_, buf_)                                                     \
    do {                                                                       \
        _Pragma("unroll")                                                      \
        for (int t = 0; t < 2; t++) {                                          \
            const int s = tid + 256 * t;                                       \
            const int r = s >> 3, c = (s & 7) << 3;                            \
            cpa16(vs_s + (uint32_t)(((buf_) * 64 * 72 + r * 72 + c) * 2),      \
                  vg + (size_t)((kt_) * 64 + r) * DH_ + c);                    \
        }                                                                      \
        cpcommit();                                                            \
    } while (0)

    // Q (group), K0 (group), V0 (group)
#pragma unroll
    for (int t = 0; t < 4; t++) {
        const int s = tid + 256 * t;
        const int r = s >> 3, c = (s & 7) << 3;
        cpa16(qs_s + (uint32_t)((r * 72 + c) * 2), qg + (size_t)r * DH_ + c);
    }
    cpcommit();
    ISSUE_K(0, 0);
    ISSUE_V(0, 0);

    // ldmatrix lane addressing
    const int a_row = wq + (l & 15);
    const int a_col = (l >> 4) << 3;
    const int kb_row = ((l >> 4) << 3) + (l & 7);
    const int kb_col = ((l >> 3) & 1) << 3;
    const int vb_row = (((l >> 3) & 1) << 3) + (l & 7);
    const int vb_col = (l >> 4) << 3;

    cpwait<2>();
    __syncthreads();

    uint32_t qa[4][4];
    const uint32_t qaddr = qs_s + (uint32_t)((a_row * 72 + a_col) * 2);
#pragma unroll
    for (int kc = 0; kc < 4; kc++)
        ldsm4(qa[kc][0], qa[kc][1], qa[kc][2], qa[kc][3], qaddr + kc * 32);

    float4 ctx[8];
#pragma unroll
    for (int j = 0; j < 8; j++) ctx[j] = make_float4(0.f, 0.f, 0.f, 0.f);
    float rs0 = 0.f, rs1 = 0.f;

    const int rg0 = q0 + wq + g;
    const int rg1 = rg0 + 8;
    const int er0 = wq + g;            // local e rows
    __half* eg = g_eh + ((size_t)bh * L_ + q0) * L_;

    for (int kt = 0; kt < 32; kt++) {
        const int buf = kt & 1;
        cpwait<1>();
        __syncthreads();

        // ---- QK^T ----
        float4 acc[8];
#pragma unroll
        for (int j = 0; j < 8; j++) acc[j] = make_float4(0.f, 0.f, 0.f, 0.f);

        const uint32_t ksb = ks_s + (uint32_t)(buf * 64 * 72 * 2);
#pragma unroll
        for (int kc = 0; kc < 4; kc++) {
#pragma unroll
            for (int q4 = 0; q4 < 4; q4++) {
                uint32_t b0, b1, b2, b3;
                ldsm4(b0, b1, b2, b3,
                      ksb + (uint32_t)(((q4 * 16 + kb_row) * 72 + kc * 16 + kb_col) * 2));
                mma_f16(acc[2 * q4],     qa[kc][0], qa[kc][1], qa[kc][2], qa[kc][3], b0, b1);
                mma_f16(acc[2 * q4 + 1], qa[kc][0], qa[kc][1], qa[kc][2], qa[kc][3], b2, b3);
            }
        }

        if (kt + 1 < 32) ISSUE_K(kt + 1, buf ^ 1);

        // ---- epilogue: bitmask exp -> es smem + register repack ----
        const uint64_t m0w =
            (*(const uint64_t*)(mbB + (size_t)rg0 * 256 + kt * 8)) >> (2 * tig);
        const uint64_t m1w =
            (*(const uint64_t*)(mbB + (size_t)rg1 * 256 + kt * 8)) >> (2 * tig);
        uint32_t plo[8], phi[8];
#pragma unroll
        for (int j = 0; j < 8; j++) {
            const unsigned t0 = (unsigned)(m0w >> (8 * j)) & 3u;
            const unsigned t1 = (unsigned)(m1w >> (8 * j)) & 3u;
            const float e0 = (t0 & 1u) ? exp2f(acc[j].x * LOG2E_DIV32) : 0.f;
            const float e1 = (t0 & 2u) ? exp2f(acc[j].y * LOG2E_DIV32) : 0.f;
            const float e2 = (t1 & 1u) ? exp2f(acc[j].z * LOG2E_DIV32) : 0.f;
            const float e3 = (t1 & 2u) ? exp2f(acc[j].w * LOG2E_DIV32) : 0.f;
            rs0 += e0 + e1;
            rs1 += e2 + e3;
            const __half2 h0 = __floats2half2_rn(e0, e1);
            const __half2 h1 = __floats2half2_rn(e2, e3);
            plo[j] = *(const uint32_t*)&h0;
            phi[j] = *(const uint32_t*)&h1;
            const int cl = 8 * j + 2 * tig;
            *(__half2*)&es[er0 * 72 + cl] = h0;
            *(__half2*)&es[(er0 + 8) * 72 + cl] = h1;
        }

        if (kt + 1 < 32) cpwait<1>(); else cpwait<0>();
        __syncthreads();   // publishes es + vs

        // ---- P @ V (A from registers) ----
        const uint32_t vsb = vs_s + (uint32_t)(buf * 64 * 72 * 2);
#pragma unroll
        for (int kc = 0; kc < 4; kc++) {
            const uint32_t a0 = plo[2 * kc], a1 = phi[2 * kc];
            const uint32_t a2 = plo[2 * kc + 1], a3 = phi[2 * kc + 1];
#pragma unroll
            for (int q4 = 0; q4 < 4; q4++) {
                uint32_t b0, b1, b2, b3;
                ldsm4t(b0, b1, b2, b3,
                       vsb + (uint32_t)(((kc * 16 + vb_row) * 72 + q4 * 16 + vb_col) * 2));
                mma_f16(ctx[2 * q4],     a0, a1, a2, a3, b0, b1);
                mma_f16(ctx[2 * q4 + 1], a0, a1, a2, a3, b2, b3);
            }
        }

        // ---- coalesced e tile store: 128 rows x 64 cols fp16 ----
#pragma unroll
        for (int t = 0; t < 4; t++) {
            const int s = tid + 256 * t;
            const int r = s >> 3, c = (s & 7) << 3;
            *(uint4*)(eg + (size_t)r * L_ + kt * 64 + c) = *(const uint4*)&es[r * 72 + c];
        }

        if (kt + 1 < 32) ISSUE_V(kt + 1, buf ^ 1);
    }

    // ---- rowsum reduce -> inv ----
    rs0 += __shfl_xor_sync(0xffffffffu, rs0, 1);
    rs0 += __shfl_xor_sync(0xffffffffu, rs0, 2);
    rs1 += __shfl_xor_sync(0xffffffffu, rs1, 1);
    rs1 += __shfl_xor_sync(0xffffffffu, rs1, 2);
    if (tig == 0) {
        red[wq + g] = rs0;
        red[wq + 8 + g] = rs1;
    }
    __syncthreads();
    if (tid < 128) {
        const float s = red[tid];
        const float iv = (s > 0.f) ? (1.f / s) : 0.f;
        g_inv[(size_t)bh * L_ + q0 + tid] = iv;
        red[tid] = iv;
    }
    __syncthreads();
    const float iv0 = red[wq + g];
    const float iv1 = red[wq + 8 + g];

    // ---- ctx write (normalized fp16) ----
#pragma unroll
    for (int j = 0; j < 8; j++) {
        const int cd = 8 * j + 2 * tig;
        *(__half2*)&g_ctxh[((size_t)bh * L_ + rg0) * DH_ + cd] =
            __floats2half2_rn(ctx[j].x * iv0, ctx[j].y * iv0);
        *(__half2*)&g_ctxh[((size_t)bh * L_ + rg1) * DH_ + cd] =
            __floats2half2_rn(ctx[j].z * iv1, ctx[j].w * iv1);
    }
    (void)dummy;
#undef ISSUE_K
#undef ISSUE_V
}

// ---------------------------------------------------------------------------
extern "C" void kernel_launch(void* const* d_in, const int* in_sizes, int n_in,
                              void* d_out, int out_size) {
    const float* Q  = (const float*)d_in[0];
    const float* K  = (const float*)d_in[1];
    const float* V  = (const float*)d_in[2];
    const int*   Mk = (const int*)d_in[3];
    const float* Wq = (const float*)d_in[4];
    const float* bq = (const float*)d_in[5];
    const float* Wk = (const float*)d_in[6];
    const float* bk = (const float*)d_in[7];
    const float* Wv = (const float*)d_in[8];
    const float* bv = (const float*)d_in[9];
    const float* Wo = (const float*)d_in[10];
    const float* bo = (const float*)d_in[11];

    float* out  = (float*)d_out;
    float* attn = out + OUT_ELEMS;   // concat(out, attn_dist)

    const int smem_gemm = (2 * 128 * 72 + 2 * 64 * 72) * 2;                  // 55296
    const int smem_attn = (128 * 72 + 4 * 64 * 72 + 128 * 72) * 2 + 128 * 4; // 74240
    cudaFuncSetAttribute(proj3, cudaFuncAttributeMaxDynamicSharedMemorySize, smem_gemm);
    cudaFuncSetAttribute(epilogue, cudaFuncAttributeMaxDynamicSharedMemorySize, smem_gemm);
    cudaFuncSetAttribute(attn_fp16, cudaFuncAttributeMaxDynamicSharedMemorySize, smem_attn);

    prep<<<2048 + 3 * 4096 + 4 * 256, 256>>>(Mk, Q, K, V, Wq, Wk, Wv, Wo);

    proj3<<<dim3(8, 64, 3), 256, smem_gemm>>>(bq, bk, bv);

    const dim3 ga(16, 32);   // q-tiles of 128, b*h
    attn_fp16<<<ga, 256, smem_attn>>>(attn);

    epilogue<<<dim3(8, 64, 2), 256, smem_gemm>>>(bo, out, attn);
}

// round 11
// speedup vs baseline: 1.2520x; 1.1620x over previous
#include <cuda_runtime.h>
#include <cuda_fp16.h>
#include <cstdint>

#define B_ 4
#define L_ 2048
#define D_ 512
#define H_ 8
#define DH_ 64
#define OUT_ELEMS (B_ * L_ * D_)          // 4194304
#define LOG2E_DIV32 0.04507129744f         // log2(e)/32

// Scratch (__device__ globals; allocation-free rule)
__device__ __half   g_qin[OUT_ELEMS];               // fp16 inputs
__device__ __half   g_kin[OUT_ELEMS];
__device__ __half   g_vin[OUT_ELEMS];
__device__ __half   g_wq[D_ * D_], g_wk[D_ * D_], g_wv[D_ * D_], g_wo[D_ * D_];
__device__ __half   g_qh[OUT_ELEMS];                // fp16 projections
__device__ __half   g_kh[OUT_ELEMS];
__device__ __half   g_vh[OUT_ELEMS];
__device__ __half   g_ctxh[OUT_ELEMS];              // fp16 attention context
__device__ float    g_inv[B_ * H_ * L_];
__device__ uint32_t g_maskb[(size_t)B_ * L_ * L_ / 32];   // 2 MB bitmask
__device__ __half   g_eh[(size_t)B_ * H_ * L_ * L_];      // 268 MB unnormalized e

// ---------------------------------------------------------------------------
// helpers
// ---------------------------------------------------------------------------
__device__ __forceinline__ void mma_f16(float4& d, uint32_t a0, uint32_t a1,
                                        uint32_t a2, uint32_t a3,
                                        uint32_t b0, uint32_t b1) {
    asm volatile(
        "mma.sync.aligned.m16n8k16.row.col.f32.f16.f16.f32 "
        "{%0,%1,%2,%3}, {%4,%5,%6,%7}, {%8,%9}, {%0,%1,%2,%3};"
        : "+f"(d.x), "+f"(d.y), "+f"(d.z), "+f"(d.w)
        : "r"(a0), "r"(a1), "r"(a2), "r"(a3), "r"(b0), "r"(b1));
}
__device__ __forceinline__ void ldsm4(uint32_t& r0, uint32_t& r1, uint32_t& r2,
                                      uint32_t& r3, uint32_t addr) {
    asm volatile("ldmatrix.sync.aligned.m8n8.x4.shared.b16 {%0,%1,%2,%3}, [%4];"
                 : "=r"(r0), "=r"(r1), "=r"(r2), "=r"(r3) : "r"(addr));
}
__device__ __forceinline__ void ldsm4t(uint32_t& r0, uint32_t& r1, uint32_t& r2,
                                       uint32_t& r3, uint32_t addr) {
    asm volatile("ldmatrix.sync.aligned.m8n8.x4.trans.shared.b16 {%0,%1,%2,%3}, [%4];"
                 : "=r"(r0), "=r"(r1), "=r"(r2), "=r"(r3) : "r"(addr));
}
__device__ __forceinline__ void cpa16(uint32_t s, const void* g) {
    asm volatile("cp.async.cg.shared.global [%0], [%1], 16;" :: "r"(s), "l"(g));
}
__device__ __forceinline__ void cpcommit() {
    asm volatile("cp.async.commit_group;" ::: "memory");
}
template <int N> __device__ __forceinline__ void cpwait() {
    asm volatile("cp.async.wait_group %0;" :: "n"(N) : "memory");
}

// ---------------------------------------------------------------------------
// prep: mask -> bitmask (warp ballot) + all fp32->fp16 converts.
// Segments: [0,2048) bitpack | [2048,14336) Q,K,V | [14336,15360) weights
// ---------------------------------------------------------------------------
__global__ __launch_bounds__(256)
void prep(const int* __restrict__ m,
          const float* __restrict__ Q, const float* __restrict__ K,
          const float* __restrict__ V, const float* __restrict__ Wq,
          const float* __restrict__ Wk, const float* __restrict__ Wv,
          const float* __restrict__ Wo) {
    int bx = blockIdx.x;
    if (bx < 2048) {
        // each warp packs 1024 ints -> 32 uint32 words
        const int wg = bx * 8 + (threadIdx.x >> 5);
        const int lane = threadIdx.x & 31;
        const size_t base = (size_t)wg * 1024;
        uint32_t word = 0;
#pragma unroll
        for (int r = 0; r < 32; r++) {
            const int v = m[base + (size_t)r * 32 + lane];
            const unsigned bits = __ballot_sync(0xffffffffu, v != 0);
            if (lane == r) word = bits;
        }
        g_maskb[base / 32 + lane] = word;
        return;
    }
    bx -= 2048;
    const float* s;
    __half* d;
    size_t i;
    if (bx < 3 * 4096) {
        const int seg = bx >> 12;
        const int b2 = bx & 4095;
        s = (seg == 0) ? Q : (seg == 1) ? K : V;
        d = (seg == 0) ? g_qin : (seg == 1) ? g_kin : g_vin;
        i = (size_t)b2 * 256 + threadIdx.x;
    } else {
        bx -= 3 * 4096;
        const int seg = bx >> 8;
        const int b2 = bx & 255;
        s = (seg == 0) ? Wq : (seg == 1) ? Wk : (seg == 2) ? Wv : Wo;
        d = (seg == 0) ? g_wq : (seg == 1) ? g_wk : (seg == 2) ? g_wv : g_wo;
        i = (size_t)b2 * 256 + threadIdx.x;
    }
    const float4 v = reinterpret_cast<const float4*>(s)[i];
    __half2 h0 = __floats2half2_rn(v.x, v.y);
    __half2 h1 = __floats2half2_rn(v.z, v.w);
    uint2 o;
    o.x = *(uint32_t*)&h0;
    o.y = *(uint32_t*)&h1;
    reinterpret_cast<uint2*>(d)[i] = o;
}

// ---------------------------------------------------------------------------
// fp16 GEMM body: C[M,512] = A[M,512] @ W[512,512] + bias (fp32 accum/bias).
// Block 128x64 via (blockIdx.x, blockIdx.y), 8 warps, warp 32x32, k-stage 64.
// ---------------------------------------------------------------------------
__device__ __forceinline__ void hgemm_issue(const __half* A, const __half* W,
                                            int m0, int n0, uint32_t as_s,
                                            uint32_t bs_s, int ki, int buf,
                                            int tid) {
    const __half* Ap = A + (size_t)m0 * 512 + ki * 64;
#pragma unroll
    for (int t = 0; t < 4; t++) {
        const int s = tid + 256 * t;
        const int r = s >> 3, c = (s & 7) << 3;
        cpa16(as_s + (uint32_t)((buf * 128 * 72 + r * 72 + c) * 2),
              Ap + (size_t)r * 512 + c);
    }
    const __half* Wp = W + (size_t)ki * 64 * 512 + n0;
#pragma unroll
    for (int t = 0; t < 2; t++) {
        const int s = tid + 256 * t;
        const int r = s >> 3, c = (s & 7) << 3;
        cpa16(bs_s + (uint32_t)((buf * 64 * 72 + r * 72 + c) * 2),
              Wp + (size_t)r * 512 + c);
    }
    cpcommit();
}

template <typename OutT>
__device__ __forceinline__ void hgemm_body(const __half* __restrict__ A,
                                           const __half* __restrict__ W,
                                           const float* __restrict__ bias,
                                           OutT* __restrict__ C) {
    extern __shared__ __half smh[];
    __half* Ah = smh;                  // [2][128][72]
    __half* Wh = smh + 2 * 128 * 72;   // [2][64][72]

    const int tid = threadIdx.x, l = tid & 31, w = tid >> 5;
    const int mg = w >> 1, ng = w & 1;
    const int wm = mg * 32, wn = ng * 32;
    const int lr = l >> 2, lc = l & 3;
    const int m0 = blockIdx.y << 7, n0 = blockIdx.x << 6;

    const uint32_t as_s = (uint32_t)__cvta_generic_to_shared(Ah);
    const uint32_t bs_s = (uint32_t)__cvta_generic_to_shared(Wh);

    const int a_row = (l & 15), a_col = (l >> 4) << 3;
    const int vb_row = (((l >> 3) & 1) << 3) + (l & 7);
    const int vb_col = (l >> 4) << 3;

    float4 acc[2][4];
#pragma unroll
    for (int m = 0; m < 2; m++)
#pragma unroll
        for (int j = 0; j < 4; j++) acc[m][j] = make_float4(0.f, 0.f, 0.f, 0.f);

    hgemm_issue(A, W, m0, n0, as_s, bs_s, 0, 0, tid);

    for (int ki = 0; ki < 8; ki++) {
        if (ki + 1 < 8) {
            hgemm_issue(A, W, m0, n0, as_s, bs_s, ki + 1, (ki + 1) & 1, tid);
            cpwait<1>();
        } else {
            cpwait<0>();
        }
        __syncthreads();

        const int buf = ki & 1;
        const uint32_t a0b = as_s + (uint32_t)((buf * 128 * 72 + (wm + a_row) * 72 + a_col) * 2);
        const uint32_t a1b = a0b + 16 * 72 * 2;
        const uint32_t wb = bs_s + (uint32_t)((buf * 64 * 72) * 2);

#pragma unroll
        for (int kc = 0; kc < 4; kc++) {
            uint32_t a0[4], a1[4];
            ldsm4(a0[0], a0[1], a0[2], a0[3], a0b + kc * 32);
            ldsm4(a1[0], a1[1], a1[2], a1[3], a1b + kc * 32);
#pragma unroll
            for (int j = 0; j < 2; j++) {
                uint32_t b0, b1, b2, b3;
                ldsm4t(b0, b1, b2, b3,
                       wb + (uint32_t)(((kc * 16 + vb_row) * 72 + wn + 16 * j + vb_col) * 2));
                mma_f16(acc[0][2 * j],     a0[0], a0[1], a0[2], a0[3], b0, b1);
                mma_f16(acc[1][2 * j],     a1[0], a1[1], a1[2], a1[3], b0, b1);
                mma_f16(acc[0][2 * j + 1], a0[0], a0[1], a0[2], a0[3], b2, b3);
                mma_f16(acc[1][2 * j + 1], a1[0], a1[1], a1[2], a1[3], b2, b3);
            }
        }
        __syncthreads();
    }

#pragma unroll
    for (int m = 0; m < 2; m++)
#pragma unroll
        for (int j = 0; j < 4; j++) {
            const int rg = m0 + wm + 16 * m + lr;
            const int cg = n0 + wn + 8 * j + 2 * lc;
            const float2 bv = *(const float2*)&bias[cg];
            if constexpr (sizeof(OutT) == 2) {
                *(__half2*)&C[(size_t)rg * 512 + cg] =
                    __floats2half2_rn(acc[m][j].x + bv.x, acc[m][j].y + bv.y);
                *(__half2*)&C[(size_t)(rg + 8) * 512 + cg] =
                    __floats2half2_rn(acc[m][j].z + bv.x, acc[m][j].w + bv.y);
            } else {
                *(float2*)&C[(size_t)rg * 512 + cg] =
                    make_float2(acc[m][j].x + bv.x, acc[m][j].y + bv.y);
                *(float2*)&C[(size_t)(rg + 8) * 512 + cg] =
                    make_float2(acc[m][j].z + bv.x, acc[m][j].w + bv.y);
            }
        }
}

// ---------------------------------------------------------------------------
// proj3: all three projection GEMMs in one launch (z selects Q/K/V).
// ---------------------------------------------------------------------------
__global__ __launch_bounds__(256, 2)
void proj3(const float* __restrict__ bq, const float* __restrict__ bk,
           const float* __restrict__ bv) {
    if (blockIdx.z == 0)      hgemm_body<__half>(g_qin, g_wq, bq, g_qh);
    else if (blockIdx.z == 1) hgemm_body<__half>(g_kin, g_wk, bk, g_kh);
    else                      hgemm_body<__half>(g_vin, g_wv, bv, g_vh);
}

// ---------------------------------------------------------------------------
// out-projection GEMM (standalone)
// ---------------------------------------------------------------------------
__global__ __launch_bounds__(256, 2)
void out_gemm(const float* __restrict__ bo, float* __restrict__ out) {
    hgemm_body<float>(g_ctxh, g_wo, bo, out);
}

// ---------------------------------------------------------------------------
// rescale: attn[row][:] = fp32(g_eh[row][:]) * g_inv[row]  (1 row per block —
// the shape that measured ~124us near the DRAM roof)
// ---------------------------------------------------------------------------
__global__ __launch_bounds__(256)
void rescale_attn(float* __restrict__ attn) {
    const int row = blockIdx.x;
    const float iv = g_inv[row];
    const uint4 u = reinterpret_cast<const uint4*>(g_eh + (size_t)row * L_)[threadIdx.x];
    float4 o0, o1;
    {
        const float2 f0 = __half22float2(*(const __half2*)&u.x);
        const float2 f1 = __half22float2(*(const __half2*)&u.y);
        o0 = make_float4(f0.x * iv, f0.y * iv, f1.x * iv, f1.y * iv);
    }
    {
        const float2 f0 = __half22float2(*(const __half2*)&u.z);
        const float2 f1 = __half22float2(*(const __half2*)&u.w);
        o1 = make_float4(f0.x * iv, f0.y * iv, f1.x * iv, f1.y * iv);
    }
    float4* dst = reinterpret_cast<float4*>(attn + (size_t)row * L_);
    dst[2 * threadIdx.x] = o0;
    dst[2 * threadIdx.x + 1] = o1;
}

// ---------------------------------------------------------------------------
// fp16 fused attention (bitmask). CTA = (bh, 128 q rows); warp owns
// 16 q-rows x 64 kv. QK -> masked exp (bitmask) -> es smem (+register
// repack) -> coalesced unnormalized-e store + PV from registers.
// ---------------------------------------------------------------------------
__global__ __launch_bounds__(256, 2)
void attn_fp16(float* __restrict__ dummy) {
    extern __shared__ __half smh[];
    __half* qs = smh;                  // [128][72]
    __half* ks = qs + 128 * 72;        // [2][64][72]
    __half* vs = ks + 2 * 64 * 72;     // [2][64][72]
    __half* es = vs + 2 * 64 * 72;     // [128][72] (64 cols used)
    float* red = (float*)(es + 128 * 72);   // [128]

    const int tid = threadIdx.x, l = tid & 31, w = tid >> 5;
    const int wq = w * 16;
    const int g = l >> 2, tig = l & 3;
    const int qt = blockIdx.x, bh = blockIdx.y, b = bh >> 3;
    const int q0 = qt * 128;

    const __half* qg = g_qh + ((size_t)bh * L_ + q0) * DH_;
    const __half* kg = g_kh + (size_t)bh * L_ * DH_;
    const __half* vg = g_vh + (size_t)bh * L_ * DH_;
    const uint8_t* mbB = (const uint8_t*)g_maskb + ((size_t)b * L_ * L_ >> 3);

    const uint32_t qs_s = (uint32_t)__cvta_generic_to_shared(qs);
    const uint32_t ks_s = (uint32_t)__cvta_generic_to_shared(ks);
    const uint32_t vs_s = (uint32_t)__cvta_generic_to_shared(vs);

#define ISSUE_K(kt_, buf_)                                                     \
    do {                                                                       \
        _Pragma("unroll")                                                      \
        for (int t = 0; t < 2; t++) {                                          \
            const int s = tid + 256 * t;                                       \
            const int r = s >> 3, c = (s & 7) << 3;                            \
            cpa16(ks_s + (uint32_t)(((buf_) * 64 * 72 + r * 72 + c) * 2),      \
                  kg + (size_t)((kt_) * 64 + r) * DH_ + c);                    \
        }                                                                      \
        cpcommit();                                                            \
    } while (0)
#define ISSUE_V(kt_, buf_)                                                     \
    do {                                                                       \
        _Pragma("unroll")                                                      \
        for (int t = 0; t < 2; t++) {                                          \
            const int s = tid + 256 * t;                                       \
            const int r = s >> 3, c = (s & 7) << 3;                            \
            cpa16(vs_s + (uint32_t)(((buf_) * 64 * 72 + r * 72 + c) * 2),      \
                  vg + (size_t)((kt_) * 64 + r) * DH_ + c);                    \
        }                                                                      \
        cpcommit();                                                            \
    } while (0)

    // Q (group), K0 (group), V0 (group)
#pragma unroll
    for (int t = 0; t < 4; t++) {
        const int s = tid + 256 * t;
        const int r = s >> 3, c = (s & 7) << 3;
        cpa16(qs_s + (uint32_t)((r * 72 + c) * 2), qg + (size_t)r * DH_ + c);
    }
    cpcommit();
    ISSUE_K(0, 0);
    ISSUE_V(0, 0);

    // ldmatrix lane addressing
    const int a_row = wq + (l & 15);
    const int a_col = (l >> 4) << 3;
    const int kb_row = ((l >> 4) << 3) + (l & 7);
    const int kb_col = ((l >> 3) & 1) << 3;
    const int vb_row = (((l >> 3) & 1) << 3) + (l & 7);
    const int vb_col = (l >> 4) << 3;

    cpwait<2>();
    __syncthreads();

    uint32_t qa[4][4];
    const uint32_t qaddr = qs_s + (uint32_t)((a_row * 72 + a_col) * 2);
#pragma unroll
    for (int kc = 0; kc < 4; kc++)
        ldsm4(qa[kc][0], qa[kc][1], qa[kc][2], qa[kc][3], qaddr + kc * 32);

    float4 ctx[8];
#pragma unroll
    for (int j = 0; j < 8; j++) ctx[j] = make_float4(0.f, 0.f, 0.f, 0.f);
    float rs0 = 0.f, rs1 = 0.f;

    const int rg0 = q0 + wq + g;
    const int rg1 = rg0 + 8;
    const int er0 = wq + g;            // local e rows
    __half* eg = g_eh + ((size_t)bh * L_ + q0) * L_;

    for (int kt = 0; kt < 32; kt++) {
        const int buf = kt & 1;
        cpwait<1>();
        __syncthreads();

        // ---- QK^T ----
        float4 acc[8];
#pragma unroll
        for (int j = 0; j < 8; j++) acc[j] = make_float4(0.f, 0.f, 0.f, 0.f);

        const uint32_t ksb = ks_s + (uint32_t)(buf * 64 * 72 * 2);
#pragma unroll
        for (int kc = 0; kc < 4; kc++) {
#pragma unroll
            for (int q4 = 0; q4 < 4; q4++) {
                uint32_t b0, b1, b2, b3;
                ldsm4(b0, b1, b2, b3,
                      ksb + (uint32_t)(((q4 * 16 + kb_row) * 72 + kc * 16 + kb_col) * 2));
                mma_f16(acc[2 * q4],     qa[kc][0], qa[kc][1], qa[kc][2], qa[kc][3], b0, b1);
                mma_f16(acc[2 * q4 + 1], qa[kc][0], qa[kc][1], qa[kc][2], qa[kc][3], b2, b3);
            }
        }

        if (kt + 1 < 32) ISSUE_K(kt + 1, buf ^ 1);

        // ---- epilogue: bitmask exp -> es smem + register repack ----
        const uint64_t m0w =
            (*(const uint64_t*)(mbB + (size_t)rg0 * 256 + kt * 8)) >> (2 * tig);
        const uint64_t m1w =
            (*(const uint64_t*)(mbB + (size_t)rg1 * 256 + kt * 8)) >> (2 * tig);
        uint32_t plo[8], phi[8];
#pragma unroll
        for (int j = 0; j < 8; j++) {
            const unsigned t0 = (unsigned)(m0w >> (8 * j)) & 3u;
            const unsigned t1 = (unsigned)(m1w >> (8 * j)) & 3u;
            const float e0 = (t0 & 1u) ? exp2f(acc[j].x * LOG2E_DIV32) : 0.f;
            const float e1 = (t0 & 2u) ? exp2f(acc[j].y * LOG2E_DIV32) : 0.f;
            const float e2 = (t1 & 1u) ? exp2f(acc[j].z * LOG2E_DIV32) : 0.f;
            const float e3 = (t1 & 2u) ? exp2f(acc[j].w * LOG2E_DIV32) : 0.f;
            rs0 += e0 + e1;
            rs1 += e2 + e3;
            const __half2 h0 = __floats2half2_rn(e0, e1);
            const __half2 h1 = __floats2half2_rn(e2, e3);
            plo[j] = *(const uint32_t*)&h0;
            phi[j] = *(const uint32_t*)&h1;
            const int cl = 8 * j + 2 * tig;
            *(__half2*)&es[er0 * 72 + cl] = h0;
            *(__half2*)&es[(er0 + 8) * 72 + cl] = h1;
        }

        if (kt + 1 < 32) cpwait<1>(); else cpwait<0>();
        __syncthreads();   // publishes es + vs

        // ---- P @ V (A from registers) ----
        const uint32_t vsb = vs_s + (uint32_t)(buf * 64 * 72 * 2);
#pragma unroll
        for (int kc = 0; kc < 4; kc++) {
            const uint32_t a0 = plo[2 * kc], a1 = phi[2 * kc];
            const uint32_t a2 = plo[2 * kc + 1], a3 = phi[2 * kc + 1];
#pragma unroll
            for (int q4 = 0; q4 < 4; q4++) {
                uint32_t b0, b1, b2, b3;
                ldsm4t(b0, b1, b2, b3,
                       vsb + (uint32_t)(((kc * 16 + vb_row) * 72 + q4 * 16 + vb_col) * 2));
                mma_f16(ctx[2 * q4],     a0, a1, a2, a3, b0, b1);
                mma_f16(ctx[2 * q4 + 1], a0, a1, a2, a3, b2, b3);
            }
        }

        // ---- coalesced e tile store: 128 rows x 64 cols fp16 ----
#pragma unroll
        for (int t = 0; t < 4; t++) {
            const int s = tid + 256 * t;
            const int r = s >> 3, c = (s & 7) << 3;
            *(uint4*)(eg + (size_t)r * L_ + kt * 64 + c) = *(const uint4*)&es[r * 72 + c];
        }

        if (kt + 1 < 32) ISSUE_V(kt + 1, buf ^ 1);
    }

    // ---- rowsum reduce -> inv ----
    rs0 += __shfl_xor_sync(0xffffffffu, rs0, 1);
    rs0 += __shfl_xor_sync(0xffffffffu, rs0, 2);
    rs1 += __shfl_xor_sync(0xffffffffu, rs1, 1);
    rs1 += __shfl_xor_sync(0xffffffffu, rs1, 2);
    if (tig == 0) {
        red[wq + g] = rs0;
        red[wq + 8 + g] = rs1;
    }
    __syncthreads();
    if (tid < 128) {
        const float s = red[tid];
        const float iv = (s > 0.f) ? (1.f / s) : 0.f;
        g_inv[(size_t)bh * L_ + q0 + tid] = iv;
        red[tid] = iv;
    }
    __syncthreads();
    const float iv0 = red[wq + g];
    const float iv1 = red[wq + 8 + g];

    // ---- ctx write (normalized fp16) ----
#pragma unroll
    for (int j = 0; j < 8; j++) {
        const int cd = 8 * j + 2 * tig;
        *(__half2*)&g_ctxh[((size_t)bh * L_ + rg0) * DH_ + cd] =
            __floats2half2_rn(ctx[j].x * iv0, ctx[j].y * iv0);
        *(__half2*)&g_ctxh[((size_t)bh * L_ + rg1) * DH_ + cd] =
            __floats2half2_rn(ctx[j].z * iv1, ctx[j].w * iv1);
    }
    (void)dummy;
#undef ISSUE_K
#undef ISSUE_V
}

// ---------------------------------------------------------------------------
extern "C" void kernel_launch(void* const* d_in, const int* in_sizes, int n_in,
                              void* d_out, int out_size) {
    const float* Q  = (const float*)d_in[0];
    const float* K  = (const float*)d_in[1];
    const float* V  = (const float*)d_in[2];
    const int*   Mk = (const int*)d_in[3];
    const float* Wq = (const float*)d_in[4];
    const float* bq = (const float*)d_in[5];
    const float* Wk = (const float*)d_in[6];
    const float* bk = (const float*)d_in[7];
    const float* Wv = (const float*)d_in[8];
    const float* bv = (const float*)d_in[9];
    const float* Wo = (const float*)d_in[10];
    const float* bo = (const float*)d_in[11];

    float* out  = (float*)d_out;
    float* attn = out + OUT_ELEMS;   // concat(out, attn_dist)

    const int smem_gemm = (2 * 128 * 72 + 2 * 64 * 72) * 2;                  // 55296
    const int smem_attn = (128 * 72 + 4 * 64 * 72 + 128 * 72) * 2 + 128 * 4; // 74240
    cudaFuncSetAttribute(proj3, cudaFuncAttributeMaxDynamicSharedMemorySize, smem_gemm);
    cudaFuncSetAttribute(out_gemm, cudaFuncAttributeMaxDynamicSharedMemorySize, smem_gemm);
    cudaFuncSetAttribute(attn_fp16, cudaFuncAttributeMaxDynamicSharedMemorySize, smem_attn);

    prep<<<2048 + 3 * 4096 + 4 * 256, 256>>>(Mk, Q, K, V, Wq, Wk, Wv, Wo);

    proj3<<<dim3(8, 64, 3), 256, smem_gemm>>>(bq, bk, bv);

    const dim3 ga(16, 32);   // q-tiles of 128, b*h
    attn_fp16<<<ga, 256, smem_attn>>>(attn);

    rescale_attn<<<B_ * H_ * L_, 256>>>(attn);

    out_gemm<<<dim3(8, 64), 256, smem_gemm>>>(bo, out);
}

// round 12
// speedup vs baseline: 1.2928x; 1.0326x over previous
#include <cuda_runtime.h>
#include <cuda_fp16.h>
#include <cstdint>

#define B_ 4
#define L_ 2048
#define D_ 512
#define H_ 8
#define DH_ 64
#define OUT_ELEMS (B_ * L_ * D_)          // 4194304
#define LOG2E_DIV32 0.04507129744f         // log2(e)/32

// Scratch (__device__ globals; allocation-free rule)
__device__ __half   g_qin[OUT_ELEMS];               // fp16 inputs
__device__ __half   g_kin[OUT_ELEMS];
__device__ __half   g_vin[OUT_ELEMS];
__device__ __half   g_wq[D_ * D_], g_wk[D_ * D_], g_wv[D_ * D_], g_wo[D_ * D_];
__device__ __half   g_qh[OUT_ELEMS];                // fp16 projections
__device__ __half   g_kh[OUT_ELEMS];
__device__ __half   g_vh[OUT_ELEMS];
__device__ __half   g_ctxh[OUT_ELEMS];              // fp16 attention context
__device__ float    g_inv[B_ * H_ * L_];
__device__ uint32_t g_maskb[(size_t)B_ * L_ * L_ / 32];   // 2 MB bitmask
__device__ __half   g_eh[(size_t)B_ * H_ * L_ * L_];      // 268 MB unnormalized e

// ---------------------------------------------------------------------------
// helpers
// ---------------------------------------------------------------------------
__device__ __forceinline__ void mma_f16(float4& d, uint32_t a0, uint32_t a1,
                                        uint32_t a2, uint32_t a3,
                                        uint32_t b0, uint32_t b1) {
    asm volatile(
        "mma.sync.aligned.m16n8k16.row.col.f32.f16.f16.f32 "
        "{%0,%1,%2,%3}, {%4,%5,%6,%7}, {%8,%9}, {%0,%1,%2,%3};"
        : "+f"(d.x), "+f"(d.y), "+f"(d.z), "+f"(d.w)
        : "r"(a0), "r"(a1), "r"(a2), "r"(a3), "r"(b0), "r"(b1));
}
__device__ __forceinline__ void ldsm4(uint32_t& r0, uint32_t& r1, uint32_t& r2,
                                      uint32_t& r3, uint32_t addr) {
    asm volatile("ldmatrix.sync.aligned.m8n8.x4.shared.b16 {%0,%1,%2,%3}, [%4];"
                 : "=r"(r0), "=r"(r1), "=r"(r2), "=r"(r3) : "r"(addr));
}
__device__ __forceinline__ void ldsm4t(uint32_t& r0, uint32_t& r1, uint32_t& r2,
                                       uint32_t& r3, uint32_t addr) {
    asm volatile("ldmatrix.sync.aligned.m8n8.x4.trans.shared.b16 {%0,%1,%2,%3}, [%4];"
                 : "=r"(r0), "=r"(r1), "=r"(r2), "=r"(r3) : "r"(addr));
}
__device__ __forceinline__ void cpa16(uint32_t s, const void* g) {
    asm volatile("cp.async.cg.shared.global [%0], [%1], 16;" :: "r"(s), "l"(g));
}
__device__ __forceinline__ void cpcommit() {
    asm volatile("cp.async.commit_group;" ::: "memory");
}
template <int N> __device__ __forceinline__ void cpwait() {
    asm volatile("cp.async.wait_group %0;" :: "n"(N) : "memory");
}

// ---------------------------------------------------------------------------
// prep: mask -> bitmask (warp ballot) + all fp32->fp16 converts.
// Segments: [0,2048) bitpack | [2048,14336) Q,K,V | [14336,15360) weights
// ---------------------------------------------------------------------------
__global__ __launch_bounds__(256)
void prep(const int* __restrict__ m,
          const float* __restrict__ Q, const float* __restrict__ K,
          const float* __restrict__ V, const float* __restrict__ Wq,
          const float* __restrict__ Wk, const float* __restrict__ Wv,
          const float* __restrict__ Wo) {
    int bx = blockIdx.x;
    if (bx < 2048) {
        // each warp packs 1024 ints -> 32 uint32 words
        const int wg = bx * 8 + (threadIdx.x >> 5);
        const int lane = threadIdx.x & 31;
        const size_t base = (size_t)wg * 1024;
        uint32_t word = 0;
#pragma unroll
        for (int r = 0; r < 32; r++) {
            const int v = m[base + (size_t)r * 32 + lane];
            const unsigned bits = __ballot_sync(0xffffffffu, v != 0);
            if (lane == r) word = bits;
        }
        g_maskb[base / 32 + lane] = word;
        return;
    }
    bx -= 2048;
    const float* s;
    __half* d;
    size_t i;
    if (bx < 3 * 4096) {
        const int seg = bx >> 12;
        const int b2 = bx & 4095;
        s = (seg == 0) ? Q : (seg == 1) ? K : V;
        d = (seg == 0) ? g_qin : (seg == 1) ? g_kin : g_vin;
        i = (size_t)b2 * 256 + threadIdx.x;
    } else {
        bx -= 3 * 4096;
        const int seg = bx >> 8;
        const int b2 = bx & 255;
        s = (seg == 0) ? Wq : (seg == 1) ? Wk : (seg == 2) ? Wv : Wo;
        d = (seg == 0) ? g_wq : (seg == 1) ? g_wk : (seg == 2) ? g_wv : g_wo;
        i = (size_t)b2 * 256 + threadIdx.x;
    }
    const float4 v = reinterpret_cast<const float4*>(s)[i];
    __half2 h0 = __floats2half2_rn(v.x, v.y);
    __half2 h1 = __floats2half2_rn(v.z, v.w);
    uint2 o;
    o.x = *(uint32_t*)&h0;
    o.y = *(uint32_t*)&h1;
    reinterpret_cast<uint2*>(d)[i] = o;
}

// ---------------------------------------------------------------------------
// fp16 GEMM body: C[M,512] = A[M,512] @ W[512,512] + bias (fp32 accum/bias).
// Block 128x64 via (blockIdx.x, blockIdx.y), 8 warps, warp 32x32, k-stage 64.
// ---------------------------------------------------------------------------
__device__ __forceinline__ void hgemm_issue(const __half* A, const __half* W,
                                            int m0, int n0, uint32_t as_s,
                                            uint32_t bs_s, int ki, int buf,
                                            int tid) {
    const __half* Ap = A + (size_t)m0 * 512 + ki * 64;
#pragma unroll
    for (int t = 0; t < 4; t++) {
        const int s = tid + 256 * t;
        const int r = s >> 3, c = (s & 7) << 3;
        cpa16(as_s + (uint32_t)((buf * 128 * 72 + r * 72 + c) * 2),
              Ap + (size_t)r * 512 + c);
    }
    const __half* Wp = W + (size_t)ki * 64 * 512 + n0;
#pragma unroll
    for (int t = 0; t < 2; t++) {
        const int s = tid + 256 * t;
        const int r = s >> 3, c = (s & 7) << 3;
        cpa16(bs_s + (uint32_t)((buf * 64 * 72 + r * 72 + c) * 2),
              Wp + (size_t)r * 512 + c);
    }
    cpcommit();
}

template <typename OutT>
__device__ __forceinline__ void hgemm_body(const __half* __restrict__ A,
                                           const __half* __restrict__ W,
                                           const float* __restrict__ bias,
                                           OutT* __restrict__ C) {
    extern __shared__ __half smh[];
    __half* Ah = smh;                  // [2][128][72]
    __half* Wh = smh + 2 * 128 * 72;   // [2][64][72]

    const int tid = threadIdx.x, l = tid & 31, w = tid >> 5;
    const int mg = w >> 1, ng = w & 1;
    const int wm = mg * 32, wn = ng * 32;
    const int lr = l >> 2, lc = l & 3;
    const int m0 = blockIdx.y << 7, n0 = blockIdx.x << 6;

    const uint32_t as_s = (uint32_t)__cvta_generic_to_shared(Ah);
    const uint32_t bs_s = (uint32_t)__cvta_generic_to_shared(Wh);

    const int a_row = (l & 15), a_col = (l >> 4) << 3;
    const int vb_row = (((l >> 3) & 1) << 3) + (l & 7);
    const int vb_col = (l >> 4) << 3;

    float4 acc[2][4];
#pragma unroll
    for (int m = 0; m < 2; m++)
#pragma unroll
        for (int j = 0; j < 4; j++) acc[m][j] = make_float4(0.f, 0.f, 0.f, 0.f);

    hgemm_issue(A, W, m0, n0, as_s, bs_s, 0, 0, tid);

    for (int ki = 0; ki < 8; ki++) {
        if (ki + 1 < 8) {
            hgemm_issue(A, W, m0, n0, as_s, bs_s, ki + 1, (ki + 1) & 1, tid);
            cpwait<1>();
        } else {
            cpwait<0>();
        }
        __syncthreads();

        const int buf = ki & 1;
        const uint32_t a0b = as_s + (uint32_t)((buf * 128 * 72 + (wm + a_row) * 72 + a_col) * 2);
        const uint32_t a1b = a0b + 16 * 72 * 2;
        const uint32_t wb = bs_s + (uint32_t)((buf * 64 * 72) * 2);

#pragma unroll
        for (int kc = 0; kc < 4; kc++) {
            uint32_t a0[4], a1[4];
            ldsm4(a0[0], a0[1], a0[2], a0[3], a0b + kc * 32);
            ldsm4(a1[0], a1[1], a1[2], a1[3], a1b + kc * 32);
#pragma unroll
            for (int j = 0; j < 2; j++) {
                uint32_t b0, b1, b2, b3;
                ldsm4t(b0, b1, b2, b3,
                       wb + (uint32_t)(((kc * 16 + vb_row) * 72 + wn + 16 * j + vb_col) * 2));
                mma_f16(acc[0][2 * j],     a0[0], a0[1], a0[2], a0[3], b0, b1);
                mma_f16(acc[1][2 * j],     a1[0], a1[1], a1[2], a1[3], b0, b1);
                mma_f16(acc[0][2 * j + 1], a0[0], a0[1], a0[2], a0[3], b2, b3);
                mma_f16(acc[1][2 * j + 1], a1[0], a1[1], a1[2], a1[3], b2, b3);
            }
        }
        __syncthreads();
    }

#pragma unroll
    for (int m = 0; m < 2; m++)
#pragma unroll
        for (int j = 0; j < 4; j++) {
            const int rg = m0 + wm + 16 * m + lr;
            const int cg = n0 + wn + 8 * j + 2 * lc;
            const float2 bv = *(const float2*)&bias[cg];
            if constexpr (sizeof(OutT) == 2) {
                *(__half2*)&C[(size_t)rg * 512 + cg] =
                    __floats2half2_rn(acc[m][j].x + bv.x, acc[m][j].y + bv.y);
                *(__half2*)&C[(size_t)(rg + 8) * 512 + cg] =
                    __floats2half2_rn(acc[m][j].z + bv.x, acc[m][j].w + bv.y);
            } else {
                *(float2*)&C[(size_t)rg * 512 + cg] =
                    make_float2(acc[m][j].x + bv.x, acc[m][j].y + bv.y);
                *(float2*)&C[(size_t)(rg + 8) * 512 + cg] =
                    make_float2(acc[m][j].z + bv.x, acc[m][j].w + bv.y);
            }
        }
}

// ---------------------------------------------------------------------------
// proj3: all three projection GEMMs in one launch (z selects Q/K/V).
// ---------------------------------------------------------------------------
__global__ __launch_bounds__(256, 2)
void proj3(const float* __restrict__ bq, const float* __restrict__ bk,
           const float* __restrict__ bv) {
    if (blockIdx.z == 0)      hgemm_body<__half>(g_qin, g_wq, bq, g_qh);
    else if (blockIdx.z == 1) hgemm_body<__half>(g_kin, g_wk, bk, g_kh);
    else                      hgemm_body<__half>(g_vin, g_wv, bv, g_vh);
}

// ---------------------------------------------------------------------------
// out-projection GEMM (standalone)
// ---------------------------------------------------------------------------
__global__ __launch_bounds__(256, 2)
void out_gemm(const float* __restrict__ bo, float* __restrict__ out) {
    hgemm_body<float>(g_ctxh, g_wo, bo, out);
}

// ---------------------------------------------------------------------------
// rescale: attn[row][:] = fp32(g_eh[row][:]) * g_inv[row].
// 2 rows per block -> 2 independent uint4 loads per thread (MLP=2);
// streaming hints (no reuse of e or attn).
// ---------------------------------------------------------------------------
__global__ __launch_bounds__(256)
void rescale_attn(float* __restrict__ attn) {
    const int row0 = blockIdx.x * 2;
    const int row1 = row0 + 1;
    const float iv0 = g_inv[row0];
    const float iv1 = g_inv[row1];
    const int tid = threadIdx.x;
    const uint4 u0 = __ldcs(&reinterpret_cast<const uint4*>(g_eh + (size_t)row0 * L_)[tid]);
    const uint4 u1 = __ldcs(&reinterpret_cast<const uint4*>(g_eh + (size_t)row1 * L_)[tid]);

    float4* d0 = reinterpret_cast<float4*>(attn + (size_t)row0 * L_);
    float4* d1 = reinterpret_cast<float4*>(attn + (size_t)row1 * L_);
    {
        const float2 f0 = __half22float2(*(const __half2*)&u0.x);
        const float2 f1 = __half22float2(*(const __half2*)&u0.y);
        const float2 f2 = __half22float2(*(const __half2*)&u0.z);
        const float2 f3 = __half22float2(*(const __half2*)&u0.w);
        __stcs(&d0[2 * tid],     make_float4(f0.x * iv0, f0.y * iv0, f1.x * iv0, f1.y * iv0));
        __stcs(&d0[2 * tid + 1], make_float4(f2.x * iv0, f2.y * iv0, f3.x * iv0, f3.y * iv0));
    }
    {
        const float2 f0 = __half22float2(*(const __half2*)&u1.x);
        const float2 f1 = __half22float2(*(const __half2*)&u1.y);
        const float2 f2 = __half22float2(*(const __half2*)&u1.z);
        const float2 f3 = __half22float2(*(const __half2*)&u1.w);
        __stcs(&d1[2 * tid],     make_float4(f0.x * iv1, f0.y * iv1, f1.x * iv1, f1.y * iv1));
        __stcs(&d1[2 * tid + 1], make_float4(f2.x * iv1, f2.y * iv1, f3.x * iv1, f3.y * iv1));
    }
}

// ---------------------------------------------------------------------------
// fp16 fused attention (bitmask, mask prefetch, store-early). CTA = (bh,
// 128 q rows); warp owns 16 q-rows x 64 kv. QK -> masked exp (bitmask) ->
// es smem (+register repack) -> coalesced unnormalized-e store, then PV
// from registers (stores drain under MMA).
// ---------------------------------------------------------------------------
__global__ __launch_bounds__(256, 2)
void attn_fp16(float* __restrict__ dummy) {
    extern __shared__ __half smh[];
    __half* qs = smh;                  // [128][72]
    __half* ks = qs + 128 * 72;        // [2][64][72]
    __half* vs = ks + 2 * 64 * 72;     // [2][64][72]
    __half* es = vs + 2 * 64 * 72;     // [128][72] (64 cols used)
    float* red = (float*)(es + 128 * 72);   // [128]

    const int tid = threadIdx.x, l = tid & 31, w = tid >> 5;
    const int wq = w * 16;
    const int g = l >> 2, tig = l & 3;
    const int qt = blockIdx.x, bh = blockIdx.y, b = bh >> 3;
    const int q0 = qt * 128;

    const __half* qg = g_qh + ((size_t)bh * L_ + q0) * DH_;
    const __half* kg = g_kh + (size_t)bh * L_ * DH_;
    const __half* vg = g_vh + (size_t)bh * L_ * DH_;
    const uint8_t* mbB = (const uint8_t*)g_maskb + ((size_t)b * L_ * L_ >> 3);

    const uint32_t qs_s = (uint32_t)__cvta_generic_to_shared(qs);
    const uint32_t ks_s = (uint32_t)__cvta_generic_to_shared(ks);
    const uint32_t vs_s = (uint32_t)__cvta_generic_to_shared(vs);

#define ISSUE_K(kt_, buf_)                                                     \
    do {                                                                       \
        _Pragma("unroll")                                                      \
        for (int t = 0; t < 2; t++) {                                          \
            const int s = tid + 256 * t;                                       \
            const int r = s >> 3, c = (s & 7) << 3;                            \
            cpa16(ks_s + (uint32_t)(((buf_) * 64 * 72 + r * 72 + c) * 2),      \
                  kg + (size_t)((kt_) * 64 + r) * DH_ + c);                    \
        }                                                                      \
        cpcommit();                                                            \
    } while (0)
#define ISSUE_V(kt_, buf_)                                                     \
    do {                                                                       \
        _Pragma("unroll")                                                      \
        for (int t = 0; t < 2; t++) {                                          \
            const int s = tid + 256 * t;                                       \
            const int r = s >> 3, c = (s & 7) << 3;                            \
            cpa16(vs_s + (uint32_t)(((buf_) * 64 * 72 + r * 72 + c) * 2),      \
                  vg + (size_t)((kt_) * 64 + r) * DH_ + c);                    \
        }                                                                      \
        cpcommit();                                                            \
    } while (0)

    // Q (group), K0 (group), V0 (group)
#pragma unroll
    for (int t = 0; t < 4; t++) {
        const int s = tid + 256 * t;
        const int r = s >> 3, c = (s & 7) << 3;
        cpa16(qs_s + (uint32_t)((r * 72 + c) * 2), qg + (size_t)r * DH_ + c);
    }
    cpcommit();
    ISSUE_K(0, 0);
    ISSUE_V(0, 0);

    // ldmatrix lane addressing
    const int a_row = wq + (l & 15);
    const int a_col = (l >> 4) << 3;
    const int kb_row = ((l >> 4) << 3) + (l & 7);
    const int kb_col = ((l >> 3) & 1) << 3;
    const int vb_row = (((l >> 3) & 1) << 3) + (l & 7);
    const int vb_col = (l >> 4) << 3;

    cpwait<2>();
    __syncthreads();

    uint32_t qa[4][4];
    const uint32_t qaddr = qs_s + (uint32_t)((a_row * 72 + a_col) * 2);
#pragma unroll
    for (int kc = 0; kc < 4; kc++)
        ldsm4(qa[kc][0], qa[kc][1], qa[kc][2], qa[kc][3], qaddr + kc * 32);

    float4 ctx[8];
#pragma unroll
    for (int j = 0; j < 8; j++) ctx[j] = make_float4(0.f, 0.f, 0.f, 0.f);
    float rs0 = 0.f, rs1 = 0.f;

    const int rg0 = q0 + wq + g;
    const int rg1 = rg0 + 8;
    const int er0 = wq + g;            // local e rows
    __half* eg = g_eh + ((size_t)bh * L_ + q0) * L_;

    // mask prefetch for kt = 0
    uint64_t m0w = (*(const uint64_t*)(mbB + (size_t)rg0 * 256)) >> (2 * tig);
    uint64_t m1w = (*(const uint64_t*)(mbB + (size_t)rg1 * 256)) >> (2 * tig);

    for (int kt = 0; kt < 32; kt++) {
        const int buf = kt & 1;
        cpwait<1>();
        __syncthreads();

        // prefetch next iteration's mask words (resolve under QK MMAs)
        uint64_t n0w = 0, n1w = 0;
        if (kt + 1 < 32) {
            n0w = (*(const uint64_t*)(mbB + (size_t)rg0 * 256 + (kt + 1) * 8)) >> (2 * tig);
            n1w = (*(const uint64_t*)(mbB + (size_t)rg1 * 256 + (kt + 1) * 8)) >> (2 * tig);
        }

        // ---- QK^T ----
        float4 acc[8];
#pragma unroll
        for (int j = 0; j < 8; j++) acc[j] = make_float4(0.f, 0.f, 0.f, 0.f);

        const uint32_t ksb = ks_s + (uint32_t)(buf * 64 * 72 * 2);
#pragma unroll
        for (int kc = 0; kc < 4; kc++) {
#pragma unroll
            for (int q4 = 0; q4 < 4; q4++) {
                uint32_t b0, b1, b2, b3;
                ldsm4(b0, b1, b2, b3,
                      ksb + (uint32_t)(((q4 * 16 + kb_row) * 72 + kc * 16 + kb_col) * 2));
                mma_f16(acc[2 * q4],     qa[kc][0], qa[kc][1], qa[kc][2], qa[kc][3], b0, b1);
                mma_f16(acc[2 * q4 + 1], qa[kc][0], qa[kc][1], qa[kc][2], qa[kc][3], b2, b3);
            }
        }

        if (kt + 1 < 32) ISSUE_K(kt + 1, buf ^ 1);

        // ---- epilogue: bitmask exp -> es smem + register repack ----
        uint32_t plo[8], phi[8];
#pragma unroll
        for (int j = 0; j < 8; j++) {
            const unsigned t0 = (unsigned)(m0w >> (8 * j)) & 3u;
            const unsigned t1 = (unsigned)(m1w >> (8 * j)) & 3u;
            const float e0 = (t0 & 1u) ? exp2f(acc[j].x * LOG2E_DIV32) : 0.f;
            const float e1 = (t0 & 2u) ? exp2f(acc[j].y * LOG2E_DIV32) : 0.f;
            const float e2 = (t1 & 1u) ? exp2f(acc[j].z * LOG2E_DIV32) : 0.f;
            const float e3 = (t1 & 2u) ? exp2f(acc[j].w * LOG2E_DIV32) : 0.f;
            rs0 += e0 + e1;
            rs1 += e2 + e3;
            const __half2 h0 = __floats2half2_rn(e0, e1);
            const __half2 h1 = __floats2half2_rn(e2, e3);
            plo[j] = *(const uint32_t*)&h0;
            phi[j] = *(const uint32_t*)&h1;
            const int cl = 8 * j + 2 * tig;
            *(__half2*)&es[er0 * 72 + cl] = h0;
            *(__half2*)&es[(er0 + 8) * 72 + cl] = h1;
        }
        m0w = n0w;
        m1w = n1w;

        if (kt + 1 < 32) cpwait<1>(); else cpwait<0>();
        __syncthreads();   // publishes es + vs

        // ---- coalesced e tile store FIRST (drains under PV MMAs) ----
#pragma unroll
        for (int t = 0; t < 4; t++) {
            const int s = tid + 256 * t;
            const int r = s >> 3, c = (s & 7) << 3;
            __stcs((uint4*)(eg + (size_t)r * L_ + kt * 64 + c), *(const uint4*)&es[r * 72 + c]);
        }

        // ---- P @ V (A from registers) ----
        const uint32_t vsb = vs_s + (uint32_t)(buf * 64 * 72 * 2);
#pragma unroll
        for (int kc = 0; kc < 4; kc++) {
            const uint32_t a0 = plo[2 * kc], a1 = phi[2 * kc];
            const uint32_t a2 = plo[2 * kc + 1], a3 = phi[2 * kc + 1];
#pragma unroll
            for (int q4 = 0; q4 < 4; q4++) {
                uint32_t b0, b1, b2, b3;
                ldsm4t(b0, b1, b2, b3,
                       vsb + (uint32_t)(((kc * 16 + vb_row) * 72 + q4 * 16 + vb_col) * 2));
                mma_f16(ctx[2 * q4],     a0, a1, a2, a3, b0, b1);
                mma_f16(ctx[2 * q4 + 1], a0, a1, a2, a3, b2, b3);
            }
        }

        if (kt + 1 < 32) ISSUE_V(kt + 1, buf ^ 1);
    }

    // ---- rowsum reduce -> inv ----
    rs0 += __shfl_xor_sync(0xffffffffu, rs0, 1);
    rs0 += __shfl_xor_sync(0xffffffffu, rs0, 2);
    rs1 += __shfl_xor_sync(0xffffffffu, rs1, 1);
    rs1 += __shfl_xor_sync(0xffffffffu, rs1, 2);
    if (tig == 0) {
        red[wq + g] = rs0;
        red[wq + 8 + g] = rs1;
    }
    __syncthreads();
    if (tid < 128) {
        const float s = red[tid];
        const float iv = (s > 0.f) ? (1.f / s) : 0.f;
        g_inv[(size_t)bh * L_ + q0 + tid] = iv;
        red[tid] = iv;
    }
    __syncthreads();
    const float iv0 = red[wq + g];
    const float iv1 = red[wq + 8 + g];

    // ---- ctx write (normalized fp16) ----
#pragma unroll
    for (int j = 0; j < 8; j++) {
        const int cd = 8 * j + 2 * tig;
        *(__half2*)&g_ctxh[((size_t)bh * L_ + rg0) * DH_ + cd] =
            __floats2half2_rn(ctx[j].x * iv0, ctx[j].y * iv0);
        *(__half2*)&g_ctxh[((size_t)bh * L_ + rg1) * DH_ + cd] =
            __floats2half2_rn(ctx[j].z * iv1, ctx[j].w * iv1);
    }
    (void)dummy;
#undef ISSUE_K
#undef ISSUE_V
}

// ---------------------------------------------------------------------------
extern "C" void kernel_launch(void* const* d_in, const int* in_sizes, int n_in,
                              void* d_out, int out_size) {
    const float* Q  = (const float*)d_in[0];
    const float* K  = (const float*)d_in[1];
    const float* V  = (const float*)d_in[2];
    const int*   Mk = (const int*)d_in[3];
    const float* Wq = (const float*)d_in[4];
    const float* bq = (const float*)d_in[5];
    const float* Wk = (const float*)d_in[6];
    const float* bk = (const float*)d_in[7];
    const float* Wv = (const float*)d_in[8];
    const float* bv = (const float*)d_in[9];
    const float* Wo = (const float*)d_in[10];
    const float* bo = (const float*)d_in[11];

    float* out  = (float*)d_out;
    float* attn = out + OUT_ELEMS;   // concat(out, attn_dist)

    const int smem_gemm = (2 * 128 * 72 + 2 * 64 * 72) * 2;                  // 55296
    const int smem_attn = (128 * 72 + 4 * 64 * 72 + 128 * 72) * 2 + 128 * 4; // 74240
    cudaFuncSetAttribute(proj3, cudaFuncAttributeMaxDynamicSharedMemorySize, smem_gemm);
    cudaFuncSetAttribute(out_gemm, cudaFuncAttributeMaxDynamicSharedMemorySize, smem_gemm);
    cudaFuncSetAttribute(attn_fp16, cudaFuncAttributeMaxDynamicSharedMemorySize, smem_attn);

    prep<<<2048 + 3 * 4096 + 4 * 256, 256>>>(Mk, Q, K, V, Wq, Wk, Wv, Wo);

    proj3<<<dim3(8, 64, 3), 256, smem_gemm>>>(bq, bk, bv);

    const dim3 ga(16, 32);   // q-tiles of 128, b*h
    attn_fp16<<<ga, 256, smem_attn>>>(attn);

    rescale_attn<<<B_ * H_ * L_ / 2, 256>>>(attn);

    out_gemm<<<dim3(8, 64), 256, smem_gemm>>>(bo, out);
}